// round 13
// baseline (speedup 1.0000x reference)
#include <cuda_runtime.h>
#include <math.h>

#define DIMN 2048
#define NH 16
#define HD 128
#define MEMN 128
#define SEQN 2048
#define BATCH 4
#define HID 5632
#define NCHUNK (SEQN / MEMN)     // 16
#define RROWS (BATCH * MEMN)     // 512 rows per step
#define TOTAL (2 * MEMN)         // 256
#define EPS 1e-5f

// ---------------- scratch (__device__ globals; no allocation) ----------------
__device__ float g_om  [RROWS * DIMN];
__device__ float g_sx  [RROWS * DIMN];
__device__ float g_om2 [RROWS * DIMN];
__device__ float g_h   [RROWS * DIMN];        // rmsnorm out / FFN out
__device__ float g_g13 [RROWS * 2 * HID];     // fused w1|w3 output
__device__ float g_om4 [RROWS * DIMN];
__device__ float g_mkv [RROWS * 2 * DIMN];    // fused mk|mv
__device__ float g_xqkv[RROWS * 3 * DIMN];    // fused xq|xk|xv
__device__ float g_q  [BATCH * NH * MEMN  * HD];
__device__ float g_k  [BATCH * NH * TOTAL * HD];
__device__ float g_v  [BATCH * NH * TOTAL * HD];
__device__ float g_s  [BATCH * NH * MEMN * TOTAL];
__device__ float g_y  [BATCH * SEQN * DIMN];

// pre-split + pre-swizzled weights (hi/lo interleaved, GEMM B-tile layout)
__device__ unsigned g_p_wm  [DIMN * DIMN * 2];
__device__ unsigned g_p_wo  [DIMN * DIMN * 2];
__device__ unsigned g_p_w2  [HID  * DIMN * 2];
__device__ unsigned g_p_qkv [DIMN * 3 * DIMN * 2];   // wq | wk | wv
__device__ unsigned g_p_kvm [DIMN * 2 * DIMN * 2];   // wkm | wvm
__device__ unsigned g_p_w13 [DIMN * 2 * HID  * 2];   // w1 | w3

// ---------------- reductions ----------------
__device__ __forceinline__ float block_sum256(float v) {
    __shared__ float sh[8];
    #pragma unroll
    for (int o = 16; o > 0; o >>= 1) v += __shfl_xor_sync(0xffffffffu, v, o);
    if ((threadIdx.x & 31) == 0) sh[threadIdx.x >> 5] = v;
    __syncthreads();
    float t = 0.f;
    if (threadIdx.x < 32) {
        t = (threadIdx.x < 8) ? sh[threadIdx.x] : 0.f;
        #pragma unroll
        for (int o = 4; o > 0; o >>= 1) t += __shfl_xor_sync(0xffffffffu, t, o);
        if (threadIdx.x == 0) sh[0] = t;
    }
    __syncthreads();
    float r = sh[0];
    __syncthreads();
    return r;
}

__device__ __forceinline__ float block_max256(float v) {
    __shared__ float sh[8];
    #pragma unroll
    for (int o = 16; o > 0; o >>= 1) v = fmaxf(v, __shfl_xor_sync(0xffffffffu, v, o));
    if ((threadIdx.x & 31) == 0) sh[threadIdx.x >> 5] = v;
    __syncthreads();
    float t = -3.4e38f;
    if (threadIdx.x < 32) {
        t = (threadIdx.x < 8) ? sh[threadIdx.x] : -3.4e38f;
        #pragma unroll
        for (int o = 4; o > 0; o >>= 1) t = fmaxf(t, __shfl_xor_sync(0xffffffffu, t, o));
        if (threadIdx.x == 0) sh[0] = t;
    }
    __syncthreads();
    float r = sh[0];
    __syncthreads();
    return r;
}

// ---------------- tf32 helpers ----------------
__device__ __forceinline__ unsigned f2tf32(float f) {
    unsigned u;
    asm("cvt.rna.tf32.f32 %0, %1;" : "=r"(u) : "f"(f));
    return u;
}

__device__ __forceinline__ void split_tf32(float f, unsigned& hi, unsigned& lo) {
    hi = f2tf32(f);
    lo = f2tf32(f - __uint_as_float(hi));
}

__device__ __forceinline__ void mma_tf32(float c[4], const unsigned a[4], const unsigned b[2]) {
    asm volatile(
        "mma.sync.aligned.m16n8k8.row.col.f32.tf32.tf32.f32 "
        "{%0,%1,%2,%3}, {%4,%5,%6,%7}, {%8,%9}, {%0,%1,%2,%3};"
        : "+f"(c[0]), "+f"(c[1]), "+f"(c[2]), "+f"(c[3])
        : "r"(a[0]), "r"(a[1]), "r"(a[2]), "r"(a[3]), "r"(b[0]), "r"(b[1]));
}

// ---------------- weight pre-split into a concatenated-N layout -------------
__global__ void __launch_bounds__(256) presplit_kernel(
    unsigned* __restrict__ dst, const float* __restrict__ src,
    int K, int N, int nt_off, int ntiles_tot)
{
    int idx = blockIdx.x * 256 + threadIdx.x;   // one float4 per thread
    int total = (K * N) >> 2;
    if (idx >= total) return;
    int nrow4 = N >> 2;
    int k  = idx / nrow4;
    int nn = (idx - k * nrow4) << 2;
    float4 v = ((const float4*)src)[idx];
    int kt = k >> 5, kr = k & 31;
    int nt = nn >> 7, nl = nn & 127;
    int nc = nl ^ ((kr & 3) * 8);
    size_t base = (((size_t)kt * ntiles_tot + nt_off + nt) << 13)
                + ((size_t)kr * 128 + nc) * 2;
    unsigned h0, l0, h1, l1, h2, l2, h3, l3;
    split_tf32(v.x, h0, l0);
    split_tf32(v.y, h1, l1);
    split_tf32(v.z, h2, l2);
    split_tf32(v.w, h3, l3);
    *(uint4*)&dst[base]     = make_uint4(h0, l0, h1, l1);
    *(uint4*)&dst[base + 4] = make_uint4(h2, l2, h3, l3);
}

// ---------------- common GEMM constants --------------------------------------
#define GBM 64
#define GBN 128
#define GBK 32
#define A_BUF_WORDS (GBM * GBK * 2)    // 16KB/stage
#define B_BUF_WORDS (GBK * GBN * 2)    // 32KB/stage (narrow)
#define GEMM_SMEM ((2 * A_BUF_WORDS + 2 * B_BUF_WORDS) * 4)       // 98304 B
#define WBN 256
#define BW_BUF_WORDS (GBK * WBN * 2)   // 64KB/stage (wide)
#define GEMM_SMEM_W ((2 * A_BUF_WORDS + 2 * BW_BUF_WORDS) * 4)    // 163840 B

// ---------------- narrow GEMM (BN=128, 2 CTA/SM) — unchanged from R12 -------
__global__ void __launch_bounds__(256) gemm_tf32x3_pw(
    const float* __restrict__ A, const unsigned* __restrict__ Bp,
    float* __restrict__ C, int M, int N, int K, int lda)
{
    extern __shared__ unsigned su[];
    typedef unsigned ABuf[GBM][GBK][2];
    typedef unsigned BBuf[GBK][GBN][2];
    ABuf* As = (ABuf*)su;
    BBuf* Bs = (BBuf*)(su + 2 * A_BUF_WORDS);

    const int tid  = threadIdx.x;
    const int lane = tid & 31;
    const int wid  = tid >> 5;
    const int warp_m = wid & 1;
    const int warp_n = wid >> 1;
    const int row0 = blockIdx.y * GBM;
    const int col0 = blockIdx.x * GBN;
    const int ntiles = N >> 7;

    unsigned sbB[2];
    sbB[0] = (unsigned)__cvta_generic_to_shared(&Bs[0][0][0][0]);
    sbB[1] = (unsigned)__cvta_generic_to_shared(&Bs[1][0][0][0]);

    float4 ra[2];
    float acc[2][4][4];
    #pragma unroll
    for (int i = 0; i < 2; i++)
        #pragma unroll
        for (int j = 0; j < 4; j++)
            #pragma unroll
            for (int l = 0; l < 4; l++) acc[i][j][l] = 0.f;

    {
        const unsigned* btile = Bp + (((size_t)0 * ntiles + (col0 >> 7)) << 13);
        #pragma unroll
        for (int i = 0; i < 8; i++) {
            unsigned d = sbB[0] + (unsigned)(tid + i * 256) * 16u;
            const unsigned* g = btile + (size_t)(tid + i * 256) * 4;
            asm volatile("cp.async.cg.shared.global [%0], [%1], 16;\n"
                         :: "r"(d), "l"(g));
        }
        asm volatile("cp.async.commit_group;\n");
    }
    #pragma unroll
    for (int i = 0; i < 2; i++) {
        int idx = tid + i * 256;
        int m = idx >> 3, k4 = idx & 7;
        ra[i] = *(const float4*)&A[(size_t)(row0 + m) * lda + k4 * 4];
    }
    #pragma unroll
    for (int i = 0; i < 2; i++) {
        int idx = tid + i * 256;
        int m = idx >> 3, k4 = idx & 7;
        int kc = (k4 * 4) ^ ((m & 7) * 4);
        unsigned h0, l0, h1, l1, h2, l2, h3, l3;
        split_tf32(ra[i].x, h0, l0);
        split_tf32(ra[i].y, h1, l1);
        split_tf32(ra[i].z, h2, l2);
        split_tf32(ra[i].w, h3, l3);
        *(uint4*)&As[0][m][kc][0]     = make_uint4(h0, l0, h1, l1);
        *(uint4*)&As[0][m][kc + 2][0] = make_uint4(h2, l2, h3, l3);
    }
    asm volatile("cp.async.wait_group 0;\n" ::: "memory");
    __syncthreads();

    int buf = 0;
    for (int kk = 0; kk < K; kk += GBK) {
        const int nxt = buf ^ 1;
        const bool more = (kk + GBK < K);

        if (more) {
            const unsigned* btile = Bp
                + (((size_t)((kk + GBK) >> 5) * ntiles + (col0 >> 7)) << 13);
            #pragma unroll
            for (int i = 0; i < 8; i++) {
                unsigned d = sbB[nxt] + (unsigned)(tid + i * 256) * 16u;
                const unsigned* g = btile + (size_t)(tid + i * 256) * 4;
                asm volatile("cp.async.cg.shared.global [%0], [%1], 16;\n"
                             :: "r"(d), "l"(g));
            }
            asm volatile("cp.async.commit_group;\n");
            #pragma unroll
            for (int i = 0; i < 2; i++) {
                int idx = tid + i * 256;
                int m = idx >> 3, k4 = idx & 7;
                ra[i] = *(const float4*)&A[(size_t)(row0 + m) * lda + kk + GBK + k4 * 4];
            }
        }

        #pragma unroll
        for (int ks = 0; ks < 4; ks++) {
            int kq = ks * 8 + (lane & 3);
            int swb = (lane & 3) * 8;
            unsigned afH[2][4], afL[2][4];
            unsigned bfH[4][2], bfL[4][2];
            #pragma unroll
            for (int mf = 0; mf < 2; mf++) {
                int m  = warp_m * 32 + mf * 16 + (lane >> 2);
                int sw = (lane >> 2) * 4;
                uint2 a0 = *(const uint2*)&As[buf][m][kq ^ sw][0];
                uint2 a1 = *(const uint2*)&As[buf][m + 8][kq ^ sw][0];
                uint2 a2 = *(const uint2*)&As[buf][m][(kq + 4) ^ sw][0];
                uint2 a3 = *(const uint2*)&As[buf][m + 8][(kq + 4) ^ sw][0];
                afH[mf][0] = a0.x; afL[mf][0] = a0.y;
                afH[mf][1] = a1.x; afL[mf][1] = a1.y;
                afH[mf][2] = a2.x; afL[mf][2] = a2.y;
                afH[mf][3] = a3.x; afL[mf][3] = a3.y;
            }
            #pragma unroll
            for (int nf = 0; nf < 4; nf++) {
                int n = warp_n * 32 + nf * 8 + (lane >> 2);
                uint2 b0 = *(const uint2*)&Bs[buf][kq][n ^ swb][0];
                uint2 b1 = *(const uint2*)&Bs[buf][kq + 4][n ^ swb][0];
                bfH[nf][0] = b0.x; bfL[nf][0] = b0.y;
                bfH[nf][1] = b1.x; bfL[nf][1] = b1.y;
            }
            #pragma unroll
            for (int mf = 0; mf < 2; mf++)
                #pragma unroll
                for (int nf = 0; nf < 4; nf++) {
                    mma_tf32(acc[mf][nf], afL[mf], bfH[nf]);
                    mma_tf32(acc[mf][nf], afH[mf], bfL[nf]);
                    mma_tf32(acc[mf][nf], afH[mf], bfH[nf]);
                }
        }

        if (more) {
            #pragma unroll
            for (int i = 0; i < 2; i++) {
                int idx = tid + i * 256;
                int m = idx >> 3, k4 = idx & 7;
                int kc = (k4 * 4) ^ ((m & 7) * 4);
                unsigned h0, l0, h1, l1, h2, l2, h3, l3;
                split_tf32(ra[i].x, h0, l0);
                split_tf32(ra[i].y, h1, l1);
                split_tf32(ra[i].z, h2, l2);
                split_tf32(ra[i].w, h3, l3);
                *(uint4*)&As[nxt][m][kc][0]     = make_uint4(h0, l0, h1, l1);
                *(uint4*)&As[nxt][m][kc + 2][0] = make_uint4(h2, l2, h3, l3);
            }
            asm volatile("cp.async.wait_group 0;\n" ::: "memory");
        }
        __syncthreads();
        buf = nxt;
    }

    #pragma unroll
    for (int mf = 0; mf < 2; mf++) {
        int row = row0 + warp_m * 32 + mf * 16 + (lane >> 2);
        #pragma unroll
        for (int nf = 0; nf < 4; nf++) {
            int col = col0 + warp_n * 32 + nf * 8 + 2 * (lane & 3);
            *(float2*)&C[(size_t)row * N + col] =
                make_float2(acc[mf][nf][0], acc[mf][nf][1]);
            *(float2*)&C[(size_t)(row + 8) * N + col] =
                make_float2(acc[mf][nf][2], acc[mf][nf][3]);
        }
    }
}

// ---------------- wide GEMM (BN=256, warp tile 32x64, 1 CTA/SM) --------------
// Same per-output math and k-order as narrow -> bit-identical results.
__global__ void __launch_bounds__(256) gemm_tf32x3_pw_wide(
    const float* __restrict__ A, const unsigned* __restrict__ Bp,
    float* __restrict__ C, int M, int N, int K, int lda)
{
    extern __shared__ unsigned su[];
    typedef unsigned ABuf[GBM][GBK][2];
    typedef unsigned BBufW[2][GBK][128][2];   // [tile][k][n][hl]
    ABuf*  As = (ABuf*)su;
    BBufW* Bs = (BBufW*)(su + 2 * A_BUF_WORDS);

    const int tid  = threadIdx.x;
    const int lane = tid & 31;
    const int wid  = tid >> 5;
    const int warp_m = wid & 1;        // 2 warps along M
    const int warp_n = wid >> 1;       // 4 warps along N (64 cols each)
    const int row0 = blockIdx.y * GBM;
    const int col0 = blockIdx.x * WBN;
    const int ntiles = N >> 7;
    const int btile0 = col0 >> 7;      // first of two adjacent 128-tiles
    const int wtile  = warp_n >> 1;    // which 128-tile this warp reads
    const int nbase  = (warp_n & 1) * 64;

    unsigned sbB[2];
    sbB[0] = (unsigned)__cvta_generic_to_shared(&Bs[0][0][0][0][0]);
    sbB[1] = (unsigned)__cvta_generic_to_shared(&Bs[1][0][0][0][0]);

    float4 ra[2];
    float acc[2][8][4];
    #pragma unroll
    for (int i = 0; i < 2; i++)
        #pragma unroll
        for (int j = 0; j < 8; j++)
            #pragma unroll
            for (int l = 0; l < 4; l++) acc[i][j][l] = 0.f;

    // prologue
    {
        const unsigned* btile = Bp + (((size_t)0 * ntiles + btile0) << 13);
        #pragma unroll
        for (int i = 0; i < 16; i++) {
            unsigned d = sbB[0] + (unsigned)(tid + i * 256) * 16u;
            const unsigned* g = btile + (size_t)(tid + i * 256) * 4;
            asm volatile("cp.async.cg.shared.global [%0], [%1], 16;\n"
                         :: "r"(d), "l"(g));
        }
        asm volatile("cp.async.commit_group;\n");
    }
    #pragma unroll
    for (int i = 0; i < 2; i++) {
        int idx = tid + i * 256;
        int m = idx >> 3, k4 = idx & 7;
        ra[i] = *(const float4*)&A[(size_t)(row0 + m) * lda + k4 * 4];
    }
    #pragma unroll
    for (int i = 0; i < 2; i++) {
        int idx = tid + i * 256;
        int m = idx >> 3, k4 = idx & 7;
        int kc = (k4 * 4) ^ ((m & 7) * 4);
        unsigned h0, l0, h1, l1, h2, l2, h3, l3;
        split_tf32(ra[i].x, h0, l0);
        split_tf32(ra[i].y, h1, l1);
        split_tf32(ra[i].z, h2, l2);
        split_tf32(ra[i].w, h3, l3);
        *(uint4*)&As[0][m][kc][0]     = make_uint4(h0, l0, h1, l1);
        *(uint4*)&As[0][m][kc + 2][0] = make_uint4(h2, l2, h3, l3);
    }
    asm volatile("cp.async.wait_group 0;\n" ::: "memory");
    __syncthreads();

    int buf = 0;
    for (int kk = 0; kk < K; kk += GBK) {
        const int nxt = buf ^ 1;
        const bool more = (kk + GBK < K);

        if (more) {
            const unsigned* btile = Bp
                + (((size_t)((kk + GBK) >> 5) * ntiles + btile0) << 13);
            #pragma unroll
            for (int i = 0; i < 16; i++) {
                unsigned d = sbB[nxt] + (unsigned)(tid + i * 256) * 16u;
                const unsigned* g = btile + (size_t)(tid + i * 256) * 4;
                asm volatile("cp.async.cg.shared.global [%0], [%1], 16;\n"
                             :: "r"(d), "l"(g));
            }
            asm volatile("cp.async.commit_group;\n");
            #pragma unroll
            for (int i = 0; i < 2; i++) {
                int idx = tid + i * 256;
                int m = idx >> 3, k4 = idx & 7;
                ra[i] = *(const float4*)&A[(size_t)(row0 + m) * lda + kk + GBK + k4 * 4];
            }
        }

        #pragma unroll
        for (int ks = 0; ks < 4; ks++) {
            int kq = ks * 8 + (lane & 3);
            int swb = (lane & 3) * 8;
            unsigned afH[2][4], afL[2][4];
            unsigned bfH[8][2], bfL[8][2];
            #pragma unroll
            for (int mf = 0; mf < 2; mf++) {
                int m  = warp_m * 32 + mf * 16 + (lane >> 2);
                int sw = (lane >> 2) * 4;
                uint2 a0 = *(const uint2*)&As[buf][m][kq ^ sw][0];
                uint2 a1 = *(const uint2*)&As[buf][m + 8][kq ^ sw][0];
                uint2 a2 = *(const uint2*)&As[buf][m][(kq + 4) ^ sw][0];
                uint2 a3 = *(const uint2*)&As[buf][m + 8][(kq + 4) ^ sw][0];
                afH[mf][0] = a0.x; afL[mf][0] = a0.y;
                afH[mf][1] = a1.x; afL[mf][1] = a1.y;
                afH[mf][2] = a2.x; afL[mf][2] = a2.y;
                afH[mf][3] = a3.x; afL[mf][3] = a3.y;
            }
            #pragma unroll
            for (int nf = 0; nf < 8; nf++) {
                int nl = nbase + nf * 8 + (lane >> 2);
                uint2 b0 = *(const uint2*)&Bs[buf][wtile][kq][nl ^ swb][0];
                uint2 b1 = *(const uint2*)&Bs[buf][wtile][kq + 4][nl ^ swb][0];
                bfH[nf][0] = b0.x; bfL[nf][0] = b0.y;
                bfH[nf][1] = b1.x; bfL[nf][1] = b1.y;
            }
            #pragma unroll
            for (int mf = 0; mf < 2; mf++)
                #pragma unroll
                for (int nf = 0; nf < 8; nf++) {
                    mma_tf32(acc[mf][nf], afL[mf], bfH[nf]);
                    mma_tf32(acc[mf][nf], afH[mf], bfL[nf]);
                    mma_tf32(acc[mf][nf], afH[mf], bfH[nf]);
                }
        }

        if (more) {
            #pragma unroll
            for (int i = 0; i < 2; i++) {
                int idx = tid + i * 256;
                int m = idx >> 3, k4 = idx & 7;
                int kc = (k4 * 4) ^ ((m & 7) * 4);
                unsigned h0, l0, h1, l1, h2, l2, h3, l3;
                split_tf32(ra[i].x, h0, l0);
                split_tf32(ra[i].y, h1, l1);
                split_tf32(ra[i].z, h2, l2);
                split_tf32(ra[i].w, h3, l3);
                *(uint4*)&As[nxt][m][kc][0]     = make_uint4(h0, l0, h1, l1);
                *(uint4*)&As[nxt][m][kc + 2][0] = make_uint4(h2, l2, h3, l3);
            }
            asm volatile("cp.async.wait_group 0;\n" ::: "memory");
        }
        __syncthreads();
        buf = nxt;
    }

    #pragma unroll
    for (int mf = 0; mf < 2; mf++) {
        int row = row0 + warp_m * 32 + mf * 16 + (lane >> 2);
        #pragma unroll
        for (int nf = 0; nf < 8; nf++) {
            int col = col0 + warp_n * 64 + nf * 8 + 2 * (lane & 3);
            *(float2*)&C[(size_t)row * N + col] =
                make_float2(acc[mf][nf][0], acc[mf][nf][1]);
            *(float2*)&C[(size_t)(row + 8) * N + col] =
                make_float2(acc[mf][nf][2], acc[mf][nf][3]);
        }
    }
}

// ---------------- gather rows of a [B][SEQ][DIM] tensor chunk into [512][DIM]
__global__ void __launch_bounds__(256) gather_rows(
    float* __restrict__ dst, const float* __restrict__ src, int chunk)
{
    int row = blockIdx.x;
    int b = row >> 7, i = row & 127;
    const float4* s = (const float4*)&src[((size_t)b * SEQN + chunk * MEMN + i) * DIMN];
    float4* d = (float4*)&dst[(size_t)row * DIMN];
    #pragma unroll
    for (int t = 0; t < 2; t++) d[threadIdx.x + t * 256] = s[threadIdx.x + t * 256];
}

// ---------------- rmsnorm ----------------------------------------------------
__global__ void __launch_bounds__(256) rmsnorm_kernel(
    float* __restrict__ out, const float* __restrict__ in, const float* __restrict__ w)
{
    int row = blockIdx.x;
    const float* xr = in + (size_t)row * DIMN;
    float vals[8];
    float ss = 0.f;
    #pragma unroll
    for (int t = 0; t < 8; t++) {
        float v = xr[threadIdx.x + t * 256];
        vals[t] = v; ss += v * v;
    }
    float tot = block_sum256(ss);
    float sc = rsqrtf(tot * (1.0f / DIMN) + EPS);
    #pragma unroll
    for (int t = 0; t < 8; t++)
        out[(size_t)row * DIMN + threadIdx.x + t * 256] =
            vals[t] * sc * w[threadIdx.x + t * 256];
}

__global__ void __launch_bounds__(256) add_rmsnorm_kernel(
    float* __restrict__ out, const float* __restrict__ a,
    const float* __restrict__ b, const float* __restrict__ w)
{
    int row = blockIdx.x;
    const float* ar = a + (size_t)row * DIMN;
    const float* br = b + (size_t)row * DIMN;
    float vals[8];
    float ss = 0.f;
    #pragma unroll
    for (int t = 0; t < 8; t++) {
        float v = ar[threadIdx.x + t * 256] + br[threadIdx.x + t * 256];
        vals[t] = v; ss += v * v;
    }
    float tot = block_sum256(ss);
    float sc = rsqrtf(tot * (1.0f / DIMN) + EPS);
    #pragma unroll
    for (int t = 0; t < 8; t++)
        out[(size_t)row * DIMN + threadIdx.x + t * 256] =
            vals[t] * sc * w[threadIdx.x + t * 256];
}

// ---------------- fused-buffer silu: g13[:, :HID] = silu(g1) * g3 -----------
__global__ void __launch_bounds__(256) silu_mul_kernel(float* __restrict__ g13)
{
    int idx = blockIdx.x * 256 + threadIdx.x;
    int n4 = RROWS * HID / 4;
    if (idx >= n4) return;
    int row = idx / (HID / 4);
    int c4  = idx - row * (HID / 4);
    float4* ap = (float4*)&g13[(size_t)row * 2 * HID + c4 * 4];
    float4 av = *ap;
    float4 bv = *(const float4*)&g13[(size_t)row * 2 * HID + HID + c4 * 4];
    av.x = av.x / (1.f + expf(-av.x)) * bv.x;
    av.y = av.y / (1.f + expf(-av.y)) * bv.y;
    av.z = av.z / (1.f + expf(-av.z)) * bv.z;
    av.w = av.w / (1.f + expf(-av.w)) * bv.w;
    *ap = av;
}

// ---------------- build K,V from fused buffers with RoPE on K ---------------
__global__ void __launch_bounds__(256) build_kv_kernel(
    const float* __restrict__ mkv, const float* __restrict__ xqkv,
    const float* __restrict__ fc, const float* __restrict__ fs,
    float* __restrict__ k, float* __restrict__ v)
{
    int idx = blockIdx.x * 256 + threadIdx.x;
    if (idx >= BATCH * TOTAL * NH * (HD / 2)) return;
    int j   = idx & 63;
    int h   = (idx >> 6) & 15;
    int pos = (idx >> 10) & 255;
    int b   = idx >> 18;
    int col = h * HD + 2 * j;
    const float *sk, *sv;
    if (pos < MEMN) {
        size_t r = (size_t)(b * MEMN + pos) * (2 * DIMN);
        sk = mkv + r + col;
        sv = mkv + r + DIMN + col;
    } else {
        size_t r = (size_t)(b * MEMN + pos - MEMN) * (3 * DIMN);
        sk = xqkv + r + DIMN + col;
        sv = xqkv + r + 2 * DIMN + col;
    }
    float c = fc[pos * 64 + j], s = fs[pos * 64 + j];
    float kr = sk[0], ki = sk[1];
    size_t o = ((size_t)(b * NH + h) * TOTAL + pos) * HD + 2 * j;
    k[o]     = kr * c - ki * s;
    k[o + 1] = kr * s + ki * c;
    v[o]     = sv[0];
    v[o + 1] = sv[1];
}

// ---------------- build Q (xq slice of fused buffer) with RoPE --------------
__global__ void __launch_bounds__(256) build_q_kernel(
    const float* __restrict__ xqkv, const float* __restrict__ fc,
    const float* __restrict__ fs, float* __restrict__ q)
{
    int idx = blockIdx.x * 256 + threadIdx.x;
    if (idx >= BATCH * MEMN * NH * (HD / 2)) return;
    int j = idx & 63;
    int h = (idx >> 6) & 15;
    int i = (idx >> 10) & 127;
    int b = idx >> 17;
    int pos = MEMN + i;
    const float* src = xqkv + (size_t)(b * MEMN + i) * (3 * DIMN) + h * HD + 2 * j;
    float c = fc[pos * 64 + j], s = fs[pos * 64 + j];
    float r = src[0], im = src[1];
    size_t o = ((size_t)(b * NH + h) * MEMN + i) * HD + 2 * j;
    q[o]     = r * c - im * s;
    q[o + 1] = r * s + im * c;
}

// ---------------- S[bh][i][j] = scale * q[bh][i]·k[bh][j] -------------------
__global__ void __launch_bounds__(256) qk_kernel(
    const float* __restrict__ q, const float* __restrict__ k,
    float* __restrict__ s, float scale)
{
    __shared__ float Qs[64][64];
    __shared__ float Ks[64][64];
    int bh = blockIdx.z;
    int i0 = blockIdx.y * 64;
    int j0 = blockIdx.x * 64;
    int tid = threadIdx.x, tx = tid & 15, ty = tid >> 4;
    const float* qb = q + (size_t)bh * MEMN * HD;
    const float* kb = k + (size_t)bh * TOTAL * HD;
    float acc[4][4] = {};

    for (int dc = 0; dc < HD; dc += 64) {
        for (int t = tid; t < 64 * 16; t += 256) {
            int r = t >> 4;
            int c4 = (t & 15) * 4;
            float4 a = *(const float4*)&qb[(size_t)(i0 + r) * HD + dc + c4];
            Qs[c4 + 0][r] = a.x; Qs[c4 + 1][r] = a.y;
            Qs[c4 + 2][r] = a.z; Qs[c4 + 3][r] = a.w;
            float4 b = *(const float4*)&kb[(size_t)(j0 + r) * HD + dc + c4];
            Ks[c4 + 0][r] = b.x; Ks[c4 + 1][r] = b.y;
            Ks[c4 + 2][r] = b.z; Ks[c4 + 3][r] = b.w;
        }
        __syncthreads();
        #pragma unroll
        for (int d = 0; d < 64; d++) {
            float4 a = *(const float4*)&Qs[d][ty * 4];
            float4 b = *(const float4*)&Ks[d][tx * 4];
            float ar[4] = {a.x, a.y, a.z, a.w};
            float br[4] = {b.x, b.y, b.z, b.w};
            #pragma unroll
            for (int i = 0; i < 4; i++)
                #pragma unroll
                for (int j = 0; j < 4; j++)
                    acc[i][j] += ar[i] * br[j];
        }
        __syncthreads();
    }
    #pragma unroll
    for (int i = 0; i < 4; i++) {
        float4 o = make_float4(acc[i][0] * scale, acc[i][1] * scale,
                               acc[i][2] * scale, acc[i][3] * scale);
        *(float4*)&s[((size_t)bh * MEMN + i0 + ty * 4 + i) * TOTAL + j0 + tx * 4] = o;
    }
}

// ---------------- causal softmax ---------------------------------------------
__global__ void __launch_bounds__(256) softmax_kernel(float* __restrict__ s)
{
    int bh = blockIdx.x >> 7;
    int i  = blockIdx.x & 127;
    float* row = s + ((size_t)bh * MEMN + i) * TOTAL;
    int tid = threadIdx.x;
    int limit = MEMN + i;
    bool valid = (tid <= limit);
    float v = valid ? row[tid] : -3.4e38f;
    float m = block_max256(v);
    float e = valid ? expf(v - m) : 0.f;
    float sum = block_sum256(e);
    row[tid] = e / sum;
}

// ---------------- O = P@V -> y chunk -----------------------------------------
__global__ void __launch_bounds__(256) pv_kernel(
    const float* __restrict__ p, const float* __restrict__ v,
    float* __restrict__ y, int chunk)
{
    __shared__ float Ps[32][64];
    __shared__ float Vs[32][128];
    int bh = blockIdx.y;
    int i0 = blockIdx.x * 64;
    int b = bh >> 4, h = bh & 15;
    int tid = threadIdx.x, tx = tid & 15, ty = tid >> 4;
    const float* pb = p + (size_t)bh * MEMN * TOTAL;
    const float* vb = v + (size_t)bh * TOTAL * HD;
    float acc[4][8] = {};

    for (int j0 = 0; j0 < TOTAL; j0 += 32) {
        for (int t = tid; t < 64 * 8; t += 256) {
            int r = t >> 3;
            int c4 = (t & 7) * 4;
            float4 a = *(const float4*)&pb[(size_t)(i0 + r) * TOTAL + j0 + c4];
            Ps[c4 + 0][r] = a.x; Ps[c4 + 1][r] = a.y;
            Ps[c4 + 2][r] = a.z; Ps[c4 + 3][r] = a.w;
        }
        for (int t = tid; t < 32 * 32; t += 256) {
            int r = t >> 5;
            int c4 = (t & 31) * 4;
            *(float4*)&Vs[r][c4] = *(const float4*)&vb[(size_t)(j0 + r) * HD + c4];
        }
        __syncthreads();
        #pragma unroll
        for (int j = 0; j < 32; j++) {
            float4 a = *(const float4*)&Ps[j][ty * 4];
            float ar[4] = {a.x, a.y, a.z, a.w};
            float4 b0 = *(const float4*)&Vs[j][tx * 8];
            float4 b1 = *(const float4*)&Vs[j][tx * 8 + 4];
            float br[8] = {b0.x, b0.y, b0.z, b0.w, b1.x, b1.y, b1.z, b1.w};
            #pragma unroll
            for (int i = 0; i < 4; i++)
                #pragma unroll
                for (int jc = 0; jc < 8; jc++)
                    acc[i][jc] += ar[i] * br[jc];
        }
        __syncthreads();
    }
    #pragma unroll
    for (int i = 0; i < 4; i++) {
        size_t row = (size_t)b * SEQN + (size_t)chunk * MEMN + i0 + ty * 4 + i;
        float4 o0 = make_float4(acc[i][0], acc[i][1], acc[i][2], acc[i][3]);
        float4 o1 = make_float4(acc[i][4], acc[i][5], acc[i][6], acc[i][7]);
        *(float4*)&y[row * DIMN + h * HD + tx * 8]     = o0;
        *(float4*)&y[row * DIMN + h * HD + tx * 8 + 4] = o1;
    }
}

// ---------------- host orchestration ----------------------------------------
static void launch_gemm(const float* A, const unsigned* Bp, float* C,
                        int M, int N, int K, int lda)
{
    if ((N % WBN) == 0 && (M / GBM) * (N / WBN) >= 128) {
        dim3 grid(N / WBN, M / GBM);
        gemm_tf32x3_pw_wide<<<grid, 256, GEMM_SMEM_W>>>(A, Bp, C, M, N, K, lda);
    } else {
        dim3 grid(N / GBN, M / GBM);
        gemm_tf32x3_pw<<<grid, 256, GEMM_SMEM>>>(A, Bp, C, M, N, K, lda);
    }
}

static void launch_presplit(unsigned* dst, const float* src, int K, int N,
                            int nt_off, int ntiles_tot)
{
    int total4 = (K * N) / 4;
    presplit_kernel<<<(total4 + 255) / 256, 256>>>(dst, src, K, N, nt_off, ntiles_tot);
}

extern "C" void kernel_launch(void* const* d_in, const int* in_sizes, int n_in,
                              void* d_out, int out_size)
{
    (void)in_sizes; (void)n_in; (void)out_size;
    const float* x   = (const float*)d_in[0];
    const float* fc  = (const float*)d_in[1];
    const float* fs  = (const float*)d_in[2];
    const float* om0 = (const float*)d_in[3];
    const float* wq  = (const float*)d_in[4];
    const float* wk  = (const float*)d_in[5];
    const float* wv  = (const float*)d_in[6];
    const float* wo  = (const float*)d_in[7];
    /* d_in[8] = wqm: unused (mq = mk and mq rows are never queried) */
    const float* wkm = (const float*)d_in[9];
    const float* wvm = (const float*)d_in[10];
    const float* wm  = (const float*)d_in[11];
    const float* ffw = (const float*)d_in[12];
    const float* w1  = (const float*)d_in[13];
    const float* w2  = (const float*)d_in[14];
    const float* w3  = (const float*)d_in[15];
    const float* mnw = (const float*)d_in[16];
    float* out = (float*)d_out;

    static int smem_configured = 0;
    if (!smem_configured) {
        cudaFuncSetAttribute(gemm_tf32x3_pw,
                             cudaFuncAttributeMaxDynamicSharedMemorySize,
                             GEMM_SMEM);
        cudaFuncSetAttribute(gemm_tf32x3_pw_wide,
                             cudaFuncAttributeMaxDynamicSharedMemorySize,
                             GEMM_SMEM_W);
        smem_configured = 1;
    }

    float *om, *sx, *om2, *h, *g13, *om4, *mkv, *xqkv, *q, *k, *v, *s, *y;
    cudaGetSymbolAddress((void**)&om,   g_om);
    cudaGetSymbolAddress((void**)&sx,   g_sx);
    cudaGetSymbolAddress((void**)&om2,  g_om2);
    cudaGetSymbolAddress((void**)&h,    g_h);
    cudaGetSymbolAddress((void**)&g13,  g_g13);
    cudaGetSymbolAddress((void**)&om4,  g_om4);
    cudaGetSymbolAddress((void**)&mkv,  g_mkv);
    cudaGetSymbolAddress((void**)&xqkv, g_xqkv);
    cudaGetSymbolAddress((void**)&q,    g_q);
    cudaGetSymbolAddress((void**)&k,    g_k);
    cudaGetSymbolAddress((void**)&v,    g_v);
    cudaGetSymbolAddress((void**)&s,    g_s);
    cudaGetSymbolAddress((void**)&y,    g_y);

    unsigned *pwm, *pwo, *pw2, *pqkv, *pkvm, *pw13;
    cudaGetSymbolAddress((void**)&pwm,  g_p_wm);
    cudaGetSymbolAddress((void**)&pwo,  g_p_wo);
    cudaGetSymbolAddress((void**)&pw2,  g_p_w2);
    cudaGetSymbolAddress((void**)&pqkv, g_p_qkv);
    cudaGetSymbolAddress((void**)&pkvm, g_p_kvm);
    cudaGetSymbolAddress((void**)&pw13, g_p_w13);

    // pre-split + pre-swizzle all weights once per launch (concatenated-N)
    launch_presplit(pwm,  wm,  DIMN, DIMN, 0, 16);
    launch_presplit(pwo,  wo,  DIMN, DIMN, 0, 16);
    launch_presplit(pw2,  w2,  HID,  DIMN, 0, 16);
    launch_presplit(pqkv, wq,  DIMN, DIMN, 0,  48);
    launch_presplit(pqkv, wk,  DIMN, DIMN, 16, 48);
    launch_presplit(pqkv, wv,  DIMN, DIMN, 32, 48);
    launch_presplit(pkvm, wkm, DIMN, DIMN, 0,  32);
    launch_presplit(pkvm, wvm, DIMN, DIMN, 16, 32);
    launch_presplit(pw13, w1,  DIMN, HID,  0,  88);
    launch_presplit(pw13, w3,  DIMN, HID,  44, 88);

    const float scale = 0.08838834764831845f;   // 1/sqrt(128)

    for (int c = 0; c < NCHUNK; c++) {
        const float* omp;
        if (c == 0) {
            omp = om0;
        } else {
            gather_rows<<<RROWS, 256>>>(om, y, c - 1);
            omp = om;
        }
        gather_rows<<<RROWS, 256>>>(sx, x, c);

        // memory-stream FFN block
        launch_gemm(omp, pwm, om2, RROWS, DIMN, DIMN, DIMN);
        rmsnorm_kernel<<<RROWS, 256>>>(h, om2, ffw);
        launch_gemm(h, pw13, g13, RROWS, 2 * HID, DIMN, DIMN);     // w1|w3 fused (wide)
        silu_mul_kernel<<<(RROWS * HID / 4 + 255) / 256, 256>>>(g13);
        launch_gemm(g13, pw2, h, RROWS, DIMN, HID, 2 * HID);       // narrow
        add_rmsnorm_kernel<<<RROWS, 256>>>(om4, om2, h, mnw);

        // fused projections
        launch_gemm(om4, pkvm, mkv,  RROWS, 2 * DIMN, DIMN, DIMN); // wide
        launch_gemm(sx,  pqkv, xqkv, RROWS, 3 * DIMN, DIMN, DIMN); // wide

        // assemble roped q/k/v
        build_kv_kernel<<<(BATCH * TOTAL * NH * 64 + 255) / 256, 256>>>(
            mkv, xqkv, fc, fs, k, v);
        build_q_kernel<<<(BATCH * MEMN * NH * 64 + 255) / 256, 256>>>(xqkv, fc, fs, q);

        // attention (only output rows MEM..2*MEM-1 are needed)
        {
            dim3 g(4, 2, BATCH * NH);
            qk_kernel<<<g, 256>>>(q, k, s, scale);
        }
        softmax_kernel<<<BATCH * NH * MEMN, 256>>>(s);
        {
            dim3 g(2, BATCH * NH);
            pv_kernel<<<g, 256>>>(s, v, y, c);
        }
    }

    // final projection: out = y @ wo  (M=8192 -> wide)
    launch_gemm(y, pwo, out, BATCH * SEQN, DIMN, DIMN, DIMN);
}

// round 14
// speedup vs baseline: 1.1449x; 1.1449x over previous
#include <cuda_runtime.h>
#include <math.h>

#define DIMN 2048
#define NH 16
#define HD 128
#define MEMN 128
#define SEQN 2048
#define BATCH 4
#define HID 5632
#define NCHUNK (SEQN / MEMN)     // 16
#define RROWS (BATCH * MEMN)     // 512 rows per step
#define TOTAL (2 * MEMN)         // 256
#define EPS 1e-5f

// ---------------- scratch (__device__ globals; no allocation) ----------------
__device__ float g_om  [RROWS * DIMN];
__device__ float g_sx  [RROWS * DIMN];
__device__ float g_om2 [RROWS * DIMN];
__device__ float g_h   [RROWS * DIMN];        // rmsnorm out / FFN out
__device__ float g_g13 [RROWS * 2 * HID];     // fused w1|w3 output
__device__ float g_om4 [RROWS * DIMN];
__device__ float g_mkv [RROWS * 2 * DIMN];    // fused mk|mv
__device__ float g_xqkv[RROWS * 3 * DIMN];    // fused xq|xk|xv
__device__ float g_q  [BATCH * NH * MEMN  * HD];
__device__ float g_k  [BATCH * NH * TOTAL * HD];
__device__ float g_v  [BATCH * NH * TOTAL * HD];
__device__ float g_s  [BATCH * NH * MEMN * TOTAL];
__device__ float g_y  [BATCH * SEQN * DIMN];

// pre-split + pre-swizzled weights (hi/lo interleaved, GEMM B-tile layout)
__device__ unsigned g_p_wm  [DIMN * DIMN * 2];
__device__ unsigned g_p_wo  [DIMN * DIMN * 2];
__device__ unsigned g_p_w2  [HID  * DIMN * 2];
__device__ unsigned g_p_qkv [DIMN * 3 * DIMN * 2];   // wq | wk | wv
__device__ unsigned g_p_kvm [DIMN * 2 * DIMN * 2];   // wkm | wvm
__device__ unsigned g_p_w13 [DIMN * 2 * HID  * 2];   // w1 | w3

// ---------------- reductions ----------------
__device__ __forceinline__ float block_sum256(float v) {
    __shared__ float sh[8];
    #pragma unroll
    for (int o = 16; o > 0; o >>= 1) v += __shfl_xor_sync(0xffffffffu, v, o);
    if ((threadIdx.x & 31) == 0) sh[threadIdx.x >> 5] = v;
    __syncthreads();
    float t = 0.f;
    if (threadIdx.x < 32) {
        t = (threadIdx.x < 8) ? sh[threadIdx.x] : 0.f;
        #pragma unroll
        for (int o = 4; o > 0; o >>= 1) t += __shfl_xor_sync(0xffffffffu, t, o);
        if (threadIdx.x == 0) sh[0] = t;
    }
    __syncthreads();
    float r = sh[0];
    __syncthreads();
    return r;
}

// ---------------- tf32 helpers ----------------
__device__ __forceinline__ unsigned f2tf32(float f) {
    unsigned u;
    asm("cvt.rna.tf32.f32 %0, %1;" : "=r"(u) : "f"(f));
    return u;
}

__device__ __forceinline__ void split_tf32(float f, unsigned& hi, unsigned& lo) {
    hi = f2tf32(f);
    lo = f2tf32(f - __uint_as_float(hi));
}

__device__ __forceinline__ void mma_tf32(float c[4], const unsigned a[4], const unsigned b[2]) {
    asm volatile(
        "mma.sync.aligned.m16n8k8.row.col.f32.tf32.tf32.f32 "
        "{%0,%1,%2,%3}, {%4,%5,%6,%7}, {%8,%9}, {%0,%1,%2,%3};"
        : "+f"(c[0]), "+f"(c[1]), "+f"(c[2]), "+f"(c[3])
        : "r"(a[0]), "r"(a[1]), "r"(a[2]), "r"(a[3]), "r"(b[0]), "r"(b[1]));
}

// ---------------- weight pre-split into a concatenated-N layout -------------
__global__ void __launch_bounds__(256) presplit_kernel(
    unsigned* __restrict__ dst, const float* __restrict__ src,
    int K, int N, int nt_off, int ntiles_tot)
{
    int idx = blockIdx.x * 256 + threadIdx.x;   // one float4 per thread
    int total = (K * N) >> 2;
    if (idx >= total) return;
    int nrow4 = N >> 2;
    int k  = idx / nrow4;
    int nn = (idx - k * nrow4) << 2;
    float4 v = ((const float4*)src)[idx];
    int kt = k >> 5, kr = k & 31;
    int nt = nn >> 7, nl = nn & 127;
    int nc = nl ^ ((kr & 3) * 8);
    size_t base = (((size_t)kt * ntiles_tot + nt_off + nt) << 13)
                + ((size_t)kr * 128 + nc) * 2;
    unsigned h0, l0, h1, l1, h2, l2, h3, l3;
    split_tf32(v.x, h0, l0);
    split_tf32(v.y, h1, l1);
    split_tf32(v.z, h2, l2);
    split_tf32(v.w, h3, l3);
    *(uint4*)&dst[base]     = make_uint4(h0, l0, h1, l1);
    *(uint4*)&dst[base + 4] = make_uint4(h2, l2, h3, l3);
}

// ---------------- narrow GEMM (BN=128, 2 CTA/SM) — R12 config (reverted) ----
#define GBM 64
#define GBN 128
#define GBK 32
#define A_BUF_WORDS (GBM * GBK * 2)    // 16KB/stage
#define B_BUF_WORDS (GBK * GBN * 2)    // 32KB/stage
#define GEMM_SMEM ((2 * A_BUF_WORDS + 2 * B_BUF_WORDS) * 4)   // 98304 B

__global__ void __launch_bounds__(256) gemm_tf32x3_pw(
    const float* __restrict__ A, const unsigned* __restrict__ Bp,
    float* __restrict__ C, int M, int N, int K, int lda)
{
    extern __shared__ unsigned su[];
    typedef unsigned ABuf[GBM][GBK][2];
    typedef unsigned BBuf[GBK][GBN][2];
    ABuf* As = (ABuf*)su;
    BBuf* Bs = (BBuf*)(su + 2 * A_BUF_WORDS);

    const int tid  = threadIdx.x;
    const int lane = tid & 31;
    const int wid  = tid >> 5;
    const int warp_m = wid & 1;
    const int warp_n = wid >> 1;
    const int row0 = blockIdx.y * GBM;
    const int col0 = blockIdx.x * GBN;
    const int ntiles = N >> 7;

    unsigned sbB[2];
    sbB[0] = (unsigned)__cvta_generic_to_shared(&Bs[0][0][0][0]);
    sbB[1] = (unsigned)__cvta_generic_to_shared(&Bs[1][0][0][0]);

    float4 ra[2];
    float acc[2][4][4];
    #pragma unroll
    for (int i = 0; i < 2; i++)
        #pragma unroll
        for (int j = 0; j < 4; j++)
            #pragma unroll
            for (int l = 0; l < 4; l++) acc[i][j][l] = 0.f;

    {
        const unsigned* btile = Bp + (((size_t)0 * ntiles + (col0 >> 7)) << 13);
        #pragma unroll
        for (int i = 0; i < 8; i++) {
            unsigned d = sbB[0] + (unsigned)(tid + i * 256) * 16u;
            const unsigned* g = btile + (size_t)(tid + i * 256) * 4;
            asm volatile("cp.async.cg.shared.global [%0], [%1], 16;\n"
                         :: "r"(d), "l"(g));
        }
        asm volatile("cp.async.commit_group;\n");
    }
    #pragma unroll
    for (int i = 0; i < 2; i++) {
        int idx = tid + i * 256;
        int m = idx >> 3, k4 = idx & 7;
        ra[i] = *(const float4*)&A[(size_t)(row0 + m) * lda + k4 * 4];
    }
    #pragma unroll
    for (int i = 0; i < 2; i++) {
        int idx = tid + i * 256;
        int m = idx >> 3, k4 = idx & 7;
        int kc = (k4 * 4) ^ ((m & 7) * 4);
        unsigned h0, l0, h1, l1, h2, l2, h3, l3;
        split_tf32(ra[i].x, h0, l0);
        split_tf32(ra[i].y, h1, l1);
        split_tf32(ra[i].z, h2, l2);
        split_tf32(ra[i].w, h3, l3);
        *(uint4*)&As[0][m][kc][0]     = make_uint4(h0, l0, h1, l1);
        *(uint4*)&As[0][m][kc + 2][0] = make_uint4(h2, l2, h3, l3);
    }
    asm volatile("cp.async.wait_group 0;\n" ::: "memory");
    __syncthreads();

    int buf = 0;
    for (int kk = 0; kk < K; kk += GBK) {
        const int nxt = buf ^ 1;
        const bool more = (kk + GBK < K);

        if (more) {
            const unsigned* btile = Bp
                + (((size_t)((kk + GBK) >> 5) * ntiles + (col0 >> 7)) << 13);
            #pragma unroll
            for (int i = 0; i < 8; i++) {
                unsigned d = sbB[nxt] + (unsigned)(tid + i * 256) * 16u;
                const unsigned* g = btile + (size_t)(tid + i * 256) * 4;
                asm volatile("cp.async.cg.shared.global [%0], [%1], 16;\n"
                             :: "r"(d), "l"(g));
            }
            asm volatile("cp.async.commit_group;\n");
            #pragma unroll
            for (int i = 0; i < 2; i++) {
                int idx = tid + i * 256;
                int m = idx >> 3, k4 = idx & 7;
                ra[i] = *(const float4*)&A[(size_t)(row0 + m) * lda + kk + GBK + k4 * 4];
            }
        }

        #pragma unroll
        for (int ks = 0; ks < 4; ks++) {
            int kq = ks * 8 + (lane & 3);
            int swb = (lane & 3) * 8;
            unsigned afH[2][4], afL[2][4];
            unsigned bfH[4][2], bfL[4][2];
            #pragma unroll
            for (int mf = 0; mf < 2; mf++) {
                int m  = warp_m * 32 + mf * 16 + (lane >> 2);
                int sw = (lane >> 2) * 4;
                uint2 a0 = *(const uint2*)&As[buf][m][kq ^ sw][0];
                uint2 a1 = *(const uint2*)&As[buf][m + 8][kq ^ sw][0];
                uint2 a2 = *(const uint2*)&As[buf][m][(kq + 4) ^ sw][0];
                uint2 a3 = *(const uint2*)&As[buf][m + 8][(kq + 4) ^ sw][0];
                afH[mf][0] = a0.x; afL[mf][0] = a0.y;
                afH[mf][1] = a1.x; afL[mf][1] = a1.y;
                afH[mf][2] = a2.x; afL[mf][2] = a2.y;
                afH[mf][3] = a3.x; afL[mf][3] = a3.y;
            }
            #pragma unroll
            for (int nf = 0; nf < 4; nf++) {
                int n = warp_n * 32 + nf * 8 + (lane >> 2);
                uint2 b0 = *(const uint2*)&Bs[buf][kq][n ^ swb][0];
                uint2 b1 = *(const uint2*)&Bs[buf][kq + 4][n ^ swb][0];
                bfH[nf][0] = b0.x; bfL[nf][0] = b0.y;
                bfH[nf][1] = b1.x; bfL[nf][1] = b1.y;
            }
            #pragma unroll
            for (int mf = 0; mf < 2; mf++)
                #pragma unroll
                for (int nf = 0; nf < 4; nf++) {
                    mma_tf32(acc[mf][nf], afL[mf], bfH[nf]);
                    mma_tf32(acc[mf][nf], afH[mf], bfL[nf]);
                    mma_tf32(acc[mf][nf], afH[mf], bfH[nf]);
                }
        }

        if (more) {
            #pragma unroll
            for (int i = 0; i < 2; i++) {
                int idx = tid + i * 256;
                int m = idx >> 3, k4 = idx & 7;
                int kc = (k4 * 4) ^ ((m & 7) * 4);
                unsigned h0, l0, h1, l1, h2, l2, h3, l3;
                split_tf32(ra[i].x, h0, l0);
                split_tf32(ra[i].y, h1, l1);
                split_tf32(ra[i].z, h2, l2);
                split_tf32(ra[i].w, h3, l3);
                *(uint4*)&As[nxt][m][kc][0]     = make_uint4(h0, l0, h1, l1);
                *(uint4*)&As[nxt][m][kc + 2][0] = make_uint4(h2, l2, h3, l3);
            }
            asm volatile("cp.async.wait_group 0;\n" ::: "memory");
        }
        __syncthreads();
        buf = nxt;
    }

    #pragma unroll
    for (int mf = 0; mf < 2; mf++) {
        int row = row0 + warp_m * 32 + mf * 16 + (lane >> 2);
        #pragma unroll
        for (int nf = 0; nf < 4; nf++) {
            int col = col0 + warp_n * 32 + nf * 8 + 2 * (lane & 3);
            *(float2*)&C[(size_t)row * N + col] =
                make_float2(acc[mf][nf][0], acc[mf][nf][1]);
            *(float2*)&C[(size_t)(row + 8) * N + col] =
                make_float2(acc[mf][nf][2], acc[mf][nf][3]);
        }
    }
}

// ---------------- gather rows of a [B][SEQ][DIM] tensor chunk into [512][DIM]
__global__ void __launch_bounds__(256) gather_rows(
    float* __restrict__ dst, const float* __restrict__ src, int chunk)
{
    int row = blockIdx.x;
    int b = row >> 7, i = row & 127;
    const float4* s = (const float4*)&src[((size_t)b * SEQN + chunk * MEMN + i) * DIMN];
    float4* d = (float4*)&dst[(size_t)row * DIMN];
    #pragma unroll
    for (int t = 0; t < 2; t++) d[threadIdx.x + t * 256] = s[threadIdx.x + t * 256];
}

// ---------------- rmsnorm ----------------------------------------------------
__global__ void __launch_bounds__(256) rmsnorm_kernel(
    float* __restrict__ out, const float* __restrict__ in, const float* __restrict__ w)
{
    int row = blockIdx.x;
    const float* xr = in + (size_t)row * DIMN;
    float vals[8];
    float ss = 0.f;
    #pragma unroll
    for (int t = 0; t < 8; t++) {
        float v = xr[threadIdx.x + t * 256];
        vals[t] = v; ss += v * v;
    }
    float tot = block_sum256(ss);
    float sc = rsqrtf(tot * (1.0f / DIMN) + EPS);
    #pragma unroll
    for (int t = 0; t < 8; t++)
        out[(size_t)row * DIMN + threadIdx.x + t * 256] =
            vals[t] * sc * w[threadIdx.x + t * 256];
}

__global__ void __launch_bounds__(256) add_rmsnorm_kernel(
    float* __restrict__ out, const float* __restrict__ a,
    const float* __restrict__ b, const float* __restrict__ w)
{
    int row = blockIdx.x;
    const float* ar = a + (size_t)row * DIMN;
    const float* br = b + (size_t)row * DIMN;
    float vals[8];
    float ss = 0.f;
    #pragma unroll
    for (int t = 0; t < 8; t++) {
        float v = ar[threadIdx.x + t * 256] + br[threadIdx.x + t * 256];
        vals[t] = v; ss += v * v;
    }
    float tot = block_sum256(ss);
    float sc = rsqrtf(tot * (1.0f / DIMN) + EPS);
    #pragma unroll
    for (int t = 0; t < 8; t++)
        out[(size_t)row * DIMN + threadIdx.x + t * 256] =
            vals[t] * sc * w[threadIdx.x + t * 256];
}

// ---------------- fused-buffer silu: g13[:, :HID] = silu(g1) * g3 -----------
__global__ void __launch_bounds__(256) silu_mul_kernel(float* __restrict__ g13)
{
    int idx = blockIdx.x * 256 + threadIdx.x;
    int n4 = RROWS * HID / 4;
    if (idx >= n4) return;
    int row = idx / (HID / 4);
    int c4  = idx - row * (HID / 4);
    float4* ap = (float4*)&g13[(size_t)row * 2 * HID + c4 * 4];
    float4 av = *ap;
    float4 bv = *(const float4*)&g13[(size_t)row * 2 * HID + HID + c4 * 4];
    av.x = av.x / (1.f + expf(-av.x)) * bv.x;
    av.y = av.y / (1.f + expf(-av.y)) * bv.y;
    av.z = av.z / (1.f + expf(-av.z)) * bv.z;
    av.w = av.w / (1.f + expf(-av.w)) * bv.w;
    *ap = av;
}

// ---------------- build K,V from fused buffers with RoPE on K ---------------
__global__ void __launch_bounds__(256) build_kv_kernel(
    const float* __restrict__ mkv, const float* __restrict__ xqkv,
    const float* __restrict__ fc, const float* __restrict__ fs,
    float* __restrict__ k, float* __restrict__ v)
{
    int idx = blockIdx.x * 256 + threadIdx.x;
    if (idx >= BATCH * TOTAL * NH * (HD / 2)) return;
    int j   = idx & 63;
    int h   = (idx >> 6) & 15;
    int pos = (idx >> 10) & 255;
    int b   = idx >> 18;
    int col = h * HD + 2 * j;
    const float *sk, *sv;
    if (pos < MEMN) {
        size_t r = (size_t)(b * MEMN + pos) * (2 * DIMN);
        sk = mkv + r + col;
        sv = mkv + r + DIMN + col;
    } else {
        size_t r = (size_t)(b * MEMN + pos - MEMN) * (3 * DIMN);
        sk = xqkv + r + DIMN + col;
        sv = xqkv + r + 2 * DIMN + col;
    }
    float c = fc[pos * 64 + j], s = fs[pos * 64 + j];
    float kr = sk[0], ki = sk[1];
    size_t o = ((size_t)(b * NH + h) * TOTAL + pos) * HD + 2 * j;
    k[o]     = kr * c - ki * s;
    k[o + 1] = kr * s + ki * c;
    v[o]     = sv[0];
    v[o + 1] = sv[1];
}

// ---------------- build Q (xq slice of fused buffer) with RoPE --------------
__global__ void __launch_bounds__(256) build_q_kernel(
    const float* __restrict__ xqkv, const float* __restrict__ fc,
    const float* __restrict__ fs, float* __restrict__ q)
{
    int idx = blockIdx.x * 256 + threadIdx.x;
    if (idx >= BATCH * MEMN * NH * (HD / 2)) return;
    int j = idx & 63;
    int h = (idx >> 6) & 15;
    int i = (idx >> 10) & 127;
    int b = idx >> 17;
    int pos = MEMN + i;
    const float* src = xqkv + (size_t)(b * MEMN + i) * (3 * DIMN) + h * HD + 2 * j;
    float c = fc[pos * 64 + j], s = fs[pos * 64 + j];
    float r = src[0], im = src[1];
    size_t o = ((size_t)(b * NH + h) * MEMN + i) * HD + 2 * j;
    q[o]     = r * c - im * s;
    q[o + 1] = r * s + im * c;
}

// ---------------- fused qk + causal softmax ----------------------------------
// grid (it=2, bh=64), block 256. Each block computes the full 64x256 score
// tile in registers (same fma math/scale as before), masks causally, then
// softmaxes rows in-register: row values live on the 16 tx-threads of a
// half-warp group, reduced via shfl_xor(1,2,4,8). Writes probabilities to s.
__global__ void __launch_bounds__(256) qk_softmax_kernel(
    const float* __restrict__ q, const float* __restrict__ k,
    float* __restrict__ s, float scale)
{
    __shared__ float Qs[64][64];   // [d][i]
    __shared__ float Ks[64][64];   // [d][j]
    int bh = blockIdx.y;
    int i0 = blockIdx.x * 64;
    int tid = threadIdx.x, tx = tid & 15, ty = tid >> 4;
    const float* qb = q + (size_t)bh * MEMN * HD;
    const float* kb = k + (size_t)bh * TOTAL * HD;

    float acc[4][16];   // [row r][jt*4 + jc]; col = jt*64 + tx*4 + jc
    #pragma unroll
    for (int r = 0; r < 4; r++)
        #pragma unroll
        for (int c = 0; c < 16; c++) acc[r][c] = 0.f;

    for (int dc = 0; dc < HD; dc += 64) {
        // load Q tile for this d-chunk (once)
        for (int t = tid; t < 64 * 16; t += 256) {
            int r = t >> 4;
            int c4 = (t & 15) * 4;
            float4 a = *(const float4*)&qb[(size_t)(i0 + r) * HD + dc + c4];
            Qs[c4 + 0][r] = a.x; Qs[c4 + 1][r] = a.y;
            Qs[c4 + 2][r] = a.z; Qs[c4 + 3][r] = a.w;
        }
        for (int jt = 0; jt < 4; jt++) {
            __syncthreads();   // Ks free (and Qs ready on first jt)
            for (int t = tid; t < 64 * 16; t += 256) {
                int r = t >> 4;
                int c4 = (t & 15) * 4;
                float4 b = *(const float4*)&kb[(size_t)(jt * 64 + r) * HD + dc + c4];
                Ks[c4 + 0][r] = b.x; Ks[c4 + 1][r] = b.y;
                Ks[c4 + 2][r] = b.z; Ks[c4 + 3][r] = b.w;
            }
            __syncthreads();
            #pragma unroll
            for (int d = 0; d < 64; d++) {
                float4 a = *(const float4*)&Qs[d][ty * 4];
                float4 b = *(const float4*)&Ks[d][tx * 4];
                float ar[4] = {a.x, a.y, a.z, a.w};
                float br[4] = {b.x, b.y, b.z, b.w};
                #pragma unroll
                for (int r = 0; r < 4; r++)
                    #pragma unroll
                    for (int jc = 0; jc < 4; jc++)
                        acc[r][jt * 4 + jc] += ar[r] * br[jc];
            }
        }
        __syncthreads();   // before Qs reload for next d-chunk
    }

    // scale + causal mask, softmax per row (across the 16 tx-threads)
    float m[4], sum[4];
    #pragma unroll
    for (int r = 0; r < 4; r++) {
        int ig = i0 + ty * 4 + r;        // query index 0..127
        int limit = MEMN + ig;           // valid keys j <= limit
        float ml = -3.4e38f;
        #pragma unroll
        for (int c = 0; c < 16; c++) {
            int j = (c >> 2) * 64 + tx * 4 + (c & 3);
            acc[r][c] = (j <= limit) ? acc[r][c] * scale : -3.4e38f;
            ml = fmaxf(ml, acc[r][c]);
        }
        #pragma unroll
        for (int o = 8; o > 0; o >>= 1)
            ml = fmaxf(ml, __shfl_xor_sync(0xffffffffu, ml, o));
        m[r] = ml;
        float sl = 0.f;
        #pragma unroll
        for (int c = 0; c < 16; c++) {
            float e = expf(acc[r][c] - ml);
            acc[r][c] = e;
            sl += e;
        }
        #pragma unroll
        for (int o = 8; o > 0; o >>= 1)
            sl += __shfl_xor_sync(0xffffffffu, sl, o);
        sum[r] = sl;
    }
    (void)m;

    #pragma unroll
    for (int r = 0; r < 4; r++) {
        int ig = i0 + ty * 4 + r;
        float inv = 1.f / sum[r];
        #pragma unroll
        for (int jt = 0; jt < 4; jt++) {
            float4 o = make_float4(acc[r][jt * 4 + 0] * inv,
                                   acc[r][jt * 4 + 1] * inv,
                                   acc[r][jt * 4 + 2] * inv,
                                   acc[r][jt * 4 + 3] * inv);
            *(float4*)&s[((size_t)bh * MEMN + ig) * TOTAL + jt * 64 + tx * 4] = o;
        }
    }
}

// ---------------- O = P@V -> y chunk -----------------------------------------
__global__ void __launch_bounds__(256) pv_kernel(
    const float* __restrict__ p, const float* __restrict__ v,
    float* __restrict__ y, int chunk)
{
    __shared__ float Ps[32][64];
    __shared__ float Vs[32][128];
    int bh = blockIdx.y;
    int i0 = blockIdx.x * 64;
    int b = bh >> 4, h = bh & 15;
    int tid = threadIdx.x, tx = tid & 15, ty = tid >> 4;
    const float* pb = p + (size_t)bh * MEMN * TOTAL;
    const float* vb = v + (size_t)bh * TOTAL * HD;
    float acc[4][8] = {};

    for (int j0 = 0; j0 < TOTAL; j0 += 32) {
        for (int t = tid; t < 64 * 8; t += 256) {
            int r = t >> 3;
            int c4 = (t & 7) * 4;
            float4 a = *(const float4*)&pb[(size_t)(i0 + r) * TOTAL + j0 + c4];
            Ps[c4 + 0][r] = a.x; Ps[c4 + 1][r] = a.y;
            Ps[c4 + 2][r] = a.z; Ps[c4 + 3][r] = a.w;
        }
        for (int t = tid; t < 32 * 32; t += 256) {
            int r = t >> 5;
            int c4 = (t & 31) * 4;
            *(float4*)&Vs[r][c4] = *(const float4*)&vb[(size_t)(j0 + r) * HD + c4];
        }
        __syncthreads();
        #pragma unroll
        for (int j = 0; j < 32; j++) {
            float4 a = *(const float4*)&Ps[j][ty * 4];
            float ar[4] = {a.x, a.y, a.z, a.w};
            float4 b0 = *(const float4*)&Vs[j][tx * 8];
            float4 b1 = *(const float4*)&Vs[j][tx * 8 + 4];
            float br[8] = {b0.x, b0.y, b0.z, b0.w, b1.x, b1.y, b1.z, b1.w};
            #pragma unroll
            for (int i = 0; i < 4; i++)
                #pragma unroll
                for (int jc = 0; jc < 8; jc++)
                    acc[i][jc] += ar[i] * br[jc];
        }
        __syncthreads();
    }
    #pragma unroll
    for (int i = 0; i < 4; i++) {
        size_t row = (size_t)b * SEQN + (size_t)chunk * MEMN + i0 + ty * 4 + i;
        float4 o0 = make_float4(acc[i][0], acc[i][1], acc[i][2], acc[i][3]);
        float4 o1 = make_float4(acc[i][4], acc[i][5], acc[i][6], acc[i][7]);
        *(float4*)&y[row * DIMN + h * HD + tx * 8]     = o0;
        *(float4*)&y[row * DIMN + h * HD + tx * 8 + 4] = o1;
    }
}

// ---------------- host orchestration ----------------------------------------
static void launch_gemm(const float* A, const unsigned* Bp, float* C,
                        int M, int N, int K, int lda)
{
    dim3 grid(N / GBN, M / GBM);
    gemm_tf32x3_pw<<<grid, 256, GEMM_SMEM>>>(A, Bp, C, M, N, K, lda);
}

static void launch_presplit(unsigned* dst, const float* src, int K, int N,
                            int nt_off, int ntiles_tot)
{
    int total4 = (K * N) / 4;
    presplit_kernel<<<(total4 + 255) / 256, 256>>>(dst, src, K, N, nt_off, ntiles_tot);
}

extern "C" void kernel_launch(void* const* d_in, const int* in_sizes, int n_in,
                              void* d_out, int out_size)
{
    (void)in_sizes; (void)n_in; (void)out_size;
    const float* x   = (const float*)d_in[0];
    const float* fc  = (const float*)d_in[1];
    const float* fs  = (const float*)d_in[2];
    const float* om0 = (const float*)d_in[3];
    const float* wq  = (const float*)d_in[4];
    const float* wk  = (const float*)d_in[5];
    const float* wv  = (const float*)d_in[6];
    const float* wo  = (const float*)d_in[7];
    /* d_in[8] = wqm: unused (mq = mk and mq rows are never queried) */
    const float* wkm = (const float*)d_in[9];
    const float* wvm = (const float*)d_in[10];
    const float* wm  = (const float*)d_in[11];
    const float* ffw = (const float*)d_in[12];
    const float* w1  = (const float*)d_in[13];
    const float* w2  = (const float*)d_in[14];
    const float* w3  = (const float*)d_in[15];
    const float* mnw = (const float*)d_in[16];
    float* out = (float*)d_out;

    static int smem_configured = 0;
    if (!smem_configured) {
        cudaFuncSetAttribute(gemm_tf32x3_pw,
                             cudaFuncAttributeMaxDynamicSharedMemorySize,
                             GEMM_SMEM);
        smem_configured = 1;
    }

    float *om, *sx, *om2, *h, *g13, *om4, *mkv, *xqkv, *q, *k, *v, *s, *y;
    cudaGetSymbolAddress((void**)&om,   g_om);
    cudaGetSymbolAddress((void**)&sx,   g_sx);
    cudaGetSymbolAddress((void**)&om2,  g_om2);
    cudaGetSymbolAddress((void**)&h,    g_h);
    cudaGetSymbolAddress((void**)&g13,  g_g13);
    cudaGetSymbolAddress((void**)&om4,  g_om4);
    cudaGetSymbolAddress((void**)&mkv,  g_mkv);
    cudaGetSymbolAddress((void**)&xqkv, g_xqkv);
    cudaGetSymbolAddress((void**)&q,    g_q);
    cudaGetSymbolAddress((void**)&k,    g_k);
    cudaGetSymbolAddress((void**)&v,    g_v);
    cudaGetSymbolAddress((void**)&s,    g_s);
    cudaGetSymbolAddress((void**)&y,    g_y);

    unsigned *pwm, *pwo, *pw2, *pqkv, *pkvm, *pw13;
    cudaGetSymbolAddress((void**)&pwm,  g_p_wm);
    cudaGetSymbolAddress((void**)&pwo,  g_p_wo);
    cudaGetSymbolAddress((void**)&pw2,  g_p_w2);
    cudaGetSymbolAddress((void**)&pqkv, g_p_qkv);
    cudaGetSymbolAddress((void**)&pkvm, g_p_kvm);
    cudaGetSymbolAddress((void**)&pw13, g_p_w13);

    // pre-split + pre-swizzle all weights once per launch (concatenated-N)
    launch_presplit(pwm,  wm,  DIMN, DIMN, 0, 16);
    launch_presplit(pwo,  wo,  DIMN, DIMN, 0, 16);
    launch_presplit(pw2,  w2,  HID,  DIMN, 0, 16);
    launch_presplit(pqkv, wq,  DIMN, DIMN, 0,  48);
    launch_presplit(pqkv, wk,  DIMN, DIMN, 16, 48);
    launch_presplit(pqkv, wv,  DIMN, DIMN, 32, 48);
    launch_presplit(pkvm, wkm, DIMN, DIMN, 0,  32);
    launch_presplit(pkvm, wvm, DIMN, DIMN, 16, 32);
    launch_presplit(pw13, w1,  DIMN, HID,  0,  88);
    launch_presplit(pw13, w3,  DIMN, HID,  44, 88);

    const float scale = 0.08838834764831845f;   // 1/sqrt(128)

    for (int c = 0; c < NCHUNK; c++) {
        const float* omp;
        if (c == 0) {
            omp = om0;
        } else {
            gather_rows<<<RROWS, 256>>>(om, y, c - 1);
            omp = om;
        }
        gather_rows<<<RROWS, 256>>>(sx, x, c);

        // memory-stream FFN block
        launch_gemm(omp, pwm, om2, RROWS, DIMN, DIMN, DIMN);
        rmsnorm_kernel<<<RROWS, 256>>>(h, om2, ffw);
        launch_gemm(h, pw13, g13, RROWS, 2 * HID, DIMN, DIMN);     // w1|w3 fused
        silu_mul_kernel<<<(RROWS * HID / 4 + 255) / 256, 256>>>(g13);
        launch_gemm(g13, pw2, h, RROWS, DIMN, HID, 2 * HID);
        add_rmsnorm_kernel<<<RROWS, 256>>>(om4, om2, h, mnw);

        // fused projections
        launch_gemm(om4, pkvm, mkv,  RROWS, 2 * DIMN, DIMN, DIMN); // wkm|wvm
        launch_gemm(sx,  pqkv, xqkv, RROWS, 3 * DIMN, DIMN, DIMN); // wq|wk|wv

        // assemble roped q/k/v
        build_kv_kernel<<<(BATCH * TOTAL * NH * 64 + 255) / 256, 256>>>(
            mkv, xqkv, fc, fs, k, v);
        build_q_kernel<<<(BATCH * MEMN * NH * 64 + 255) / 256, 256>>>(xqkv, fc, fs, q);

        // attention: fused scores+softmax, then PV
        {
            dim3 g(2, BATCH * NH);
            qk_softmax_kernel<<<g, 256>>>(q, k, s, scale);
        }
        {
            dim3 g(2, BATCH * NH);
            pv_kernel<<<g, 256>>>(s, v, y, c);
        }
    }

    // final projection: out = y @ wo
    launch_gemm(y, pwo, out, BATCH * SEQN, DIMN, DIMN, DIMN);
}

// round 15
// speedup vs baseline: 1.1627x; 1.0156x over previous
#include <cuda_runtime.h>
#include <math.h>

#define DIMN 2048
#define NH 16
#define HD 128
#define MEMN 128
#define SEQN 2048
#define BATCH 4
#define HID 5632
#define NCHUNK (SEQN / MEMN)     // 16
#define RROWS (BATCH * MEMN)     // 512 rows per step
#define TOTAL (2 * MEMN)         // 256
#define EPS 1e-5f

// ---------------- scratch (__device__ globals; no allocation) ----------------
__device__ float g_om  [RROWS * DIMN];
__device__ float g_sx  [RROWS * DIMN];
__device__ float g_om2 [RROWS * DIMN];
__device__ float g_h   [RROWS * DIMN];        // rmsnorm out / FFN out
__device__ float g_g13 [RROWS * 2 * HID];     // fused w1|w3 output
__device__ float g_om4 [RROWS * DIMN];
__device__ float g_mkv [RROWS * 2 * DIMN];    // fused mk|mv
__device__ float g_xqkv[RROWS * 3 * DIMN];    // fused xq|xk|xv
__device__ float g_q  [BATCH * NH * MEMN  * HD];
__device__ float g_k  [BATCH * NH * TOTAL * HD];
__device__ float g_v  [BATCH * NH * TOTAL * HD];
__device__ float g_s  [BATCH * NH * MEMN * TOTAL];
__device__ float g_y  [BATCH * SEQN * DIMN];

// pre-split + pre-swizzled weights (hi/lo interleaved, GEMM B-tile layout)
__device__ unsigned g_p_wm  [DIMN * DIMN * 2];
__device__ unsigned g_p_wo  [DIMN * DIMN * 2];
__device__ unsigned g_p_w2  [HID  * DIMN * 2];
__device__ unsigned g_p_qkv [DIMN * 3 * DIMN * 2];   // wq | wk | wv
__device__ unsigned g_p_kvm [DIMN * 2 * DIMN * 2];   // wkm | wvm
__device__ unsigned g_p_w13 [DIMN * 2 * HID  * 2];   // w1 | w3

// ---------------- reductions ----------------
__device__ __forceinline__ float block_sum256(float v) {
    __shared__ float sh[8];
    #pragma unroll
    for (int o = 16; o > 0; o >>= 1) v += __shfl_xor_sync(0xffffffffu, v, o);
    if ((threadIdx.x & 31) == 0) sh[threadIdx.x >> 5] = v;
    __syncthreads();
    float t = 0.f;
    if (threadIdx.x < 32) {
        t = (threadIdx.x < 8) ? sh[threadIdx.x] : 0.f;
        #pragma unroll
        for (int o = 4; o > 0; o >>= 1) t += __shfl_xor_sync(0xffffffffu, t, o);
        if (threadIdx.x == 0) sh[0] = t;
    }
    __syncthreads();
    float r = sh[0];
    __syncthreads();
    return r;
}

// ---------------- tf32 helpers ----------------
__device__ __forceinline__ unsigned f2tf32(float f) {
    unsigned u;
    asm("cvt.rna.tf32.f32 %0, %1;" : "=r"(u) : "f"(f));
    return u;
}

__device__ __forceinline__ void split_tf32(float f, unsigned& hi, unsigned& lo) {
    hi = f2tf32(f);
    lo = f2tf32(f - __uint_as_float(hi));
}

__device__ __forceinline__ void mma_tf32(float c[4], const unsigned a[4], const unsigned b[2]) {
    asm volatile(
        "mma.sync.aligned.m16n8k8.row.col.f32.tf32.tf32.f32 "
        "{%0,%1,%2,%3}, {%4,%5,%6,%7}, {%8,%9}, {%0,%1,%2,%3};"
        : "+f"(c[0]), "+f"(c[1]), "+f"(c[2]), "+f"(c[3])
        : "r"(a[0]), "r"(a[1]), "r"(a[2]), "r"(a[3]), "r"(b[0]), "r"(b[1]));
}

// ---------------- weight pre-split into a concatenated-N layout -------------
__global__ void __launch_bounds__(256) presplit_kernel(
    unsigned* __restrict__ dst, const float* __restrict__ src,
    int K, int N, int nt_off, int ntiles_tot)
{
    int idx = blockIdx.x * 256 + threadIdx.x;   // one float4 per thread
    int total = (K * N) >> 2;
    if (idx >= total) return;
    int nrow4 = N >> 2;
    int k  = idx / nrow4;
    int nn = (idx - k * nrow4) << 2;
    float4 v = ((const float4*)src)[idx];
    int kt = k >> 5, kr = k & 31;
    int nt = nn >> 7, nl = nn & 127;
    int nc = nl ^ ((kr & 3) * 8);
    size_t base = (((size_t)kt * ntiles_tot + nt_off + nt) << 13)
                + ((size_t)kr * 128 + nc) * 2;
    unsigned h0, l0, h1, l1, h2, l2, h3, l3;
    split_tf32(v.x, h0, l0);
    split_tf32(v.y, h1, l1);
    split_tf32(v.z, h2, l2);
    split_tf32(v.w, h3, l3);
    *(uint4*)&dst[base]     = make_uint4(h0, l0, h1, l1);
    *(uint4*)&dst[base + 4] = make_uint4(h2, l2, h3, l3);
}

// ---------------- narrow GEMM (BN=128, 2 CTA/SM) ------------------------------
#define GBM 64
#define GBN 128
#define GBK 32
#define A_BUF_WORDS (GBM * GBK * 2)    // 16KB/stage
#define B_BUF_WORDS (GBK * GBN * 2)    // 32KB/stage
#define GEMM_SMEM ((2 * A_BUF_WORDS + 2 * B_BUF_WORDS) * 4)   // 98304 B

__global__ void __launch_bounds__(256) gemm_tf32x3_pw(
    const float* __restrict__ A, const unsigned* __restrict__ Bp,
    float* __restrict__ C, int M, int N, int K, int lda)
{
    extern __shared__ unsigned su[];
    typedef unsigned ABuf[GBM][GBK][2];
    typedef unsigned BBuf[GBK][GBN][2];
    ABuf* As = (ABuf*)su;
    BBuf* Bs = (BBuf*)(su + 2 * A_BUF_WORDS);

    const int tid  = threadIdx.x;
    const int lane = tid & 31;
    const int wid  = tid >> 5;
    const int warp_m = wid & 1;
    const int warp_n = wid >> 1;
    const int row0 = blockIdx.y * GBM;
    const int col0 = blockIdx.x * GBN;
    const int ntiles = N >> 7;

    unsigned sbB[2];
    sbB[0] = (unsigned)__cvta_generic_to_shared(&Bs[0][0][0][0]);
    sbB[1] = (unsigned)__cvta_generic_to_shared(&Bs[1][0][0][0]);

    float4 ra[2];
    float acc[2][4][4];
    #pragma unroll
    for (int i = 0; i < 2; i++)
        #pragma unroll
        for (int j = 0; j < 4; j++)
            #pragma unroll
            for (int l = 0; l < 4; l++) acc[i][j][l] = 0.f;

    {
        const unsigned* btile = Bp + (((size_t)0 * ntiles + (col0 >> 7)) << 13);
        #pragma unroll
        for (int i = 0; i < 8; i++) {
            unsigned d = sbB[0] + (unsigned)(tid + i * 256) * 16u;
            const unsigned* g = btile + (size_t)(tid + i * 256) * 4;
            asm volatile("cp.async.cg.shared.global [%0], [%1], 16;\n"
                         :: "r"(d), "l"(g));
        }
        asm volatile("cp.async.commit_group;\n");
    }
    #pragma unroll
    for (int i = 0; i < 2; i++) {
        int idx = tid + i * 256;
        int m = idx >> 3, k4 = idx & 7;
        ra[i] = *(const float4*)&A[(size_t)(row0 + m) * lda + k4 * 4];
    }
    #pragma unroll
    for (int i = 0; i < 2; i++) {
        int idx = tid + i * 256;
        int m = idx >> 3, k4 = idx & 7;
        int kc = (k4 * 4) ^ ((m & 7) * 4);
        unsigned h0, l0, h1, l1, h2, l2, h3, l3;
        split_tf32(ra[i].x, h0, l0);
        split_tf32(ra[i].y, h1, l1);
        split_tf32(ra[i].z, h2, l2);
        split_tf32(ra[i].w, h3, l3);
        *(uint4*)&As[0][m][kc][0]     = make_uint4(h0, l0, h1, l1);
        *(uint4*)&As[0][m][kc + 2][0] = make_uint4(h2, l2, h3, l3);
    }
    asm volatile("cp.async.wait_group 0;\n" ::: "memory");
    __syncthreads();

    int buf = 0;
    for (int kk = 0; kk < K; kk += GBK) {
        const int nxt = buf ^ 1;
        const bool more = (kk + GBK < K);

        if (more) {
            const unsigned* btile = Bp
                + (((size_t)((kk + GBK) >> 5) * ntiles + (col0 >> 7)) << 13);
            #pragma unroll
            for (int i = 0; i < 8; i++) {
                unsigned d = sbB[nxt] + (unsigned)(tid + i * 256) * 16u;
                const unsigned* g = btile + (size_t)(tid + i * 256) * 4;
                asm volatile("cp.async.cg.shared.global [%0], [%1], 16;\n"
                             :: "r"(d), "l"(g));
            }
            asm volatile("cp.async.commit_group;\n");
            #pragma unroll
            for (int i = 0; i < 2; i++) {
                int idx = tid + i * 256;
                int m = idx >> 3, k4 = idx & 7;
                ra[i] = *(const float4*)&A[(size_t)(row0 + m) * lda + kk + GBK + k4 * 4];
            }
        }

        #pragma unroll
        for (int ks = 0; ks < 4; ks++) {
            int kq = ks * 8 + (lane & 3);
            int swb = (lane & 3) * 8;
            unsigned afH[2][4], afL[2][4];
            unsigned bfH[4][2], bfL[4][2];
            #pragma unroll
            for (int mf = 0; mf < 2; mf++) {
                int m  = warp_m * 32 + mf * 16 + (lane >> 2);
                int sw = (lane >> 2) * 4;
                uint2 a0 = *(const uint2*)&As[buf][m][kq ^ sw][0];
                uint2 a1 = *(const uint2*)&As[buf][m + 8][kq ^ sw][0];
                uint2 a2 = *(const uint2*)&As[buf][m][(kq + 4) ^ sw][0];
                uint2 a3 = *(const uint2*)&As[buf][m + 8][(kq + 4) ^ sw][0];
                afH[mf][0] = a0.x; afL[mf][0] = a0.y;
                afH[mf][1] = a1.x; afL[mf][1] = a1.y;
                afH[mf][2] = a2.x; afL[mf][2] = a2.y;
                afH[mf][3] = a3.x; afL[mf][3] = a3.y;
            }
            #pragma unroll
            for (int nf = 0; nf < 4; nf++) {
                int n = warp_n * 32 + nf * 8 + (lane >> 2);
                uint2 b0 = *(const uint2*)&Bs[buf][kq][n ^ swb][0];
                uint2 b1 = *(const uint2*)&Bs[buf][kq + 4][n ^ swb][0];
                bfH[nf][0] = b0.x; bfL[nf][0] = b0.y;
                bfH[nf][1] = b1.x; bfL[nf][1] = b1.y;
            }
            #pragma unroll
            for (int mf = 0; mf < 2; mf++)
                #pragma unroll
                for (int nf = 0; nf < 4; nf++) {
                    mma_tf32(acc[mf][nf], afL[mf], bfH[nf]);
                    mma_tf32(acc[mf][nf], afH[mf], bfL[nf]);
                    mma_tf32(acc[mf][nf], afH[mf], bfH[nf]);
                }
        }

        if (more) {
            #pragma unroll
            for (int i = 0; i < 2; i++) {
                int idx = tid + i * 256;
                int m = idx >> 3, k4 = idx & 7;
                int kc = (k4 * 4) ^ ((m & 7) * 4);
                unsigned h0, l0, h1, l1, h2, l2, h3, l3;
                split_tf32(ra[i].x, h0, l0);
                split_tf32(ra[i].y, h1, l1);
                split_tf32(ra[i].z, h2, l2);
                split_tf32(ra[i].w, h3, l3);
                *(uint4*)&As[nxt][m][kc][0]     = make_uint4(h0, l0, h1, l1);
                *(uint4*)&As[nxt][m][kc + 2][0] = make_uint4(h2, l2, h3, l3);
            }
            asm volatile("cp.async.wait_group 0;\n" ::: "memory");
        }
        __syncthreads();
        buf = nxt;
    }

    #pragma unroll
    for (int mf = 0; mf < 2; mf++) {
        int row = row0 + warp_m * 32 + mf * 16 + (lane >> 2);
        #pragma unroll
        for (int nf = 0; nf < 4; nf++) {
            int col = col0 + warp_n * 32 + nf * 8 + 2 * (lane & 3);
            *(float2*)&C[(size_t)row * N + col] =
                make_float2(acc[mf][nf][0], acc[mf][nf][1]);
            *(float2*)&C[(size_t)(row + 8) * N + col] =
                make_float2(acc[mf][nf][2], acc[mf][nf][3]);
        }
    }
}

// ---------------- gather rows of a [B][SEQ][DIM] tensor chunk into [512][DIM]
__global__ void __launch_bounds__(256) gather_rows(
    float* __restrict__ dst, const float* __restrict__ src, int chunk)
{
    int row = blockIdx.x;
    int b = row >> 7, i = row & 127;
    const float4* s = (const float4*)&src[((size_t)b * SEQN + chunk * MEMN + i) * DIMN];
    float4* d = (float4*)&dst[(size_t)row * DIMN];
    #pragma unroll
    for (int t = 0; t < 2; t++) d[threadIdx.x + t * 256] = s[threadIdx.x + t * 256];
}

// ---------------- rmsnorm ----------------------------------------------------
__global__ void __launch_bounds__(256) rmsnorm_kernel(
    float* __restrict__ out, const float* __restrict__ in, const float* __restrict__ w)
{
    int row = blockIdx.x;
    const float* xr = in + (size_t)row * DIMN;
    float vals[8];
    float ss = 0.f;
    #pragma unroll
    for (int t = 0; t < 8; t++) {
        float v = xr[threadIdx.x + t * 256];
        vals[t] = v; ss += v * v;
    }
    float tot = block_sum256(ss);
    float sc = rsqrtf(tot * (1.0f / DIMN) + EPS);
    #pragma unroll
    for (int t = 0; t < 8; t++)
        out[(size_t)row * DIMN + threadIdx.x + t * 256] =
            vals[t] * sc * w[threadIdx.x + t * 256];
}

__global__ void __launch_bounds__(256) add_rmsnorm_kernel(
    float* __restrict__ out, const float* __restrict__ a,
    const float* __restrict__ b, const float* __restrict__ w)
{
    int row = blockIdx.x;
    const float* ar = a + (size_t)row * DIMN;
    const float* br = b + (size_t)row * DIMN;
    float vals[8];
    float ss = 0.f;
    #pragma unroll
    for (int t = 0; t < 8; t++) {
        float v = ar[threadIdx.x + t * 256] + br[threadIdx.x + t * 256];
        vals[t] = v; ss += v * v;
    }
    float tot = block_sum256(ss);
    float sc = rsqrtf(tot * (1.0f / DIMN) + EPS);
    #pragma unroll
    for (int t = 0; t < 8; t++)
        out[(size_t)row * DIMN + threadIdx.x + t * 256] =
            vals[t] * sc * w[threadIdx.x + t * 256];
}

// ---------------- fused-buffer silu: g13[:, :HID] = silu(g1) * g3 -----------
__global__ void __launch_bounds__(256) silu_mul_kernel(float* __restrict__ g13)
{
    int idx = blockIdx.x * 256 + threadIdx.x;
    int n4 = RROWS * HID / 4;
    if (idx >= n4) return;
    int row = idx / (HID / 4);
    int c4  = idx - row * (HID / 4);
    float4* ap = (float4*)&g13[(size_t)row * 2 * HID + c4 * 4];
    float4 av = *ap;
    float4 bv = *(const float4*)&g13[(size_t)row * 2 * HID + HID + c4 * 4];
    av.x = av.x / (1.f + expf(-av.x)) * bv.x;
    av.y = av.y / (1.f + expf(-av.y)) * bv.y;
    av.z = av.z / (1.f + expf(-av.z)) * bv.z;
    av.w = av.w / (1.f + expf(-av.w)) * bv.w;
    *ap = av;
}

// ---------------- build K,V from fused buffers with RoPE on K ---------------
__global__ void __launch_bounds__(256) build_kv_kernel(
    const float* __restrict__ mkv, const float* __restrict__ xqkv,
    const float* __restrict__ fc, const float* __restrict__ fs,
    float* __restrict__ k, float* __restrict__ v)
{
    int idx = blockIdx.x * 256 + threadIdx.x;
    if (idx >= BATCH * TOTAL * NH * (HD / 2)) return;
    int j   = idx & 63;
    int h   = (idx >> 6) & 15;
    int pos = (idx >> 10) & 255;
    int b   = idx >> 18;
    int col = h * HD + 2 * j;
    const float *sk, *sv;
    if (pos < MEMN) {
        size_t r = (size_t)(b * MEMN + pos) * (2 * DIMN);
        sk = mkv + r + col;
        sv = mkv + r + DIMN + col;
    } else {
        size_t r = (size_t)(b * MEMN + pos - MEMN) * (3 * DIMN);
        sk = xqkv + r + DIMN + col;
        sv = xqkv + r + 2 * DIMN + col;
    }
    float c = fc[pos * 64 + j], s = fs[pos * 64 + j];
    float kr = sk[0], ki = sk[1];
    size_t o = ((size_t)(b * NH + h) * TOTAL + pos) * HD + 2 * j;
    k[o]     = kr * c - ki * s;
    k[o + 1] = kr * s + ki * c;
    v[o]     = sv[0];
    v[o + 1] = sv[1];
}

// ---------------- build Q (xq slice of fused buffer) with RoPE --------------
__global__ void __launch_bounds__(256) build_q_kernel(
    const float* __restrict__ xqkv, const float* __restrict__ fc,
    const float* __restrict__ fs, float* __restrict__ q)
{
    int idx = blockIdx.x * 256 + threadIdx.x;
    if (idx >= BATCH * MEMN * NH * (HD / 2)) return;
    int j = idx & 63;
    int h = (idx >> 6) & 15;
    int i = (idx >> 10) & 127;
    int b = idx >> 17;
    int pos = MEMN + i;
    const float* src = xqkv + (size_t)(b * MEMN + i) * (3 * DIMN) + h * HD + 2 * j;
    float c = fc[pos * 64 + j], s = fs[pos * 64 + j];
    float r = src[0], im = src[1];
    size_t o = ((size_t)(b * NH + h) * MEMN + i) * HD + 2 * j;
    q[o]     = r * c - im * s;
    q[o + 1] = r * s + im * c;
}

// ---------------- fused qk + causal softmax ----------------------------------
__global__ void __launch_bounds__(256) qk_softmax_kernel(
    const float* __restrict__ q, const float* __restrict__ k,
    float* __restrict__ s, float scale)
{
    __shared__ float Qs[64][64];
    __shared__ float Ks[64][64];
    int bh = blockIdx.y;
    int i0 = blockIdx.x * 64;
    int tid = threadIdx.x, tx = tid & 15, ty = tid >> 4;
    const float* qb = q + (size_t)bh * MEMN * HD;
    const float* kb = k + (size_t)bh * TOTAL * HD;

    float acc[4][16];
    #pragma unroll
    for (int r = 0; r < 4; r++)
        #pragma unroll
        for (int c = 0; c < 16; c++) acc[r][c] = 0.f;

    for (int dc = 0; dc < HD; dc += 64) {
        for (int t = tid; t < 64 * 16; t += 256) {
            int r = t >> 4;
            int c4 = (t & 15) * 4;
            float4 a = *(const float4*)&qb[(size_t)(i0 + r) * HD + dc + c4];
            Qs[c4 + 0][r] = a.x; Qs[c4 + 1][r] = a.y;
            Qs[c4 + 2][r] = a.z; Qs[c4 + 3][r] = a.w;
        }
        for (int jt = 0; jt < 4; jt++) {
            __syncthreads();
            for (int t = tid; t < 64 * 16; t += 256) {
                int r = t >> 4;
                int c4 = (t & 15) * 4;
                float4 b = *(const float4*)&kb[(size_t)(jt * 64 + r) * HD + dc + c4];
                Ks[c4 + 0][r] = b.x; Ks[c4 + 1][r] = b.y;
                Ks[c4 + 2][r] = b.z; Ks[c4 + 3][r] = b.w;
            }
            __syncthreads();
            #pragma unroll
            for (int d = 0; d < 64; d++) {
                float4 a = *(const float4*)&Qs[d][ty * 4];
                float4 b = *(const float4*)&Ks[d][tx * 4];
                float ar[4] = {a.x, a.y, a.z, a.w};
                float br[4] = {b.x, b.y, b.z, b.w};
                #pragma unroll
                for (int r = 0; r < 4; r++)
                    #pragma unroll
                    for (int jc = 0; jc < 4; jc++)
                        acc[r][jt * 4 + jc] += ar[r] * br[jc];
            }
        }
        __syncthreads();
    }

    float sum[4];
    #pragma unroll
    for (int r = 0; r < 4; r++) {
        int ig = i0 + ty * 4 + r;
        int limit = MEMN + ig;
        float ml = -3.4e38f;
        #pragma unroll
        for (int c = 0; c < 16; c++) {
            int j = (c >> 2) * 64 + tx * 4 + (c & 3);
            acc[r][c] = (j <= limit) ? acc[r][c] * scale : -3.4e38f;
            ml = fmaxf(ml, acc[r][c]);
        }
        #pragma unroll
        for (int o = 8; o > 0; o >>= 1)
            ml = fmaxf(ml, __shfl_xor_sync(0xffffffffu, ml, o));
        float sl = 0.f;
        #pragma unroll
        for (int c = 0; c < 16; c++) {
            float e = expf(acc[r][c] - ml);
            acc[r][c] = e;
            sl += e;
        }
        #pragma unroll
        for (int o = 8; o > 0; o >>= 1)
            sl += __shfl_xor_sync(0xffffffffu, sl, o);
        sum[r] = sl;
    }

    #pragma unroll
    for (int r = 0; r < 4; r++) {
        int ig = i0 + ty * 4 + r;
        float inv = 1.f / sum[r];
        #pragma unroll
        for (int jt = 0; jt < 4; jt++) {
            float4 o = make_float4(acc[r][jt * 4 + 0] * inv,
                                   acc[r][jt * 4 + 1] * inv,
                                   acc[r][jt * 4 + 2] * inv,
                                   acc[r][jt * 4 + 3] * inv);
            *(float4*)&s[((size_t)bh * MEMN + ig) * TOTAL + jt * 64 + tx * 4] = o;
        }
    }
}

// ---------------- O = P@V -> y chunk -----------------------------------------
__global__ void __launch_bounds__(256) pv_kernel(
    const float* __restrict__ p, const float* __restrict__ v,
    float* __restrict__ y, int chunk)
{
    __shared__ float Ps[32][64];
    __shared__ float Vs[32][128];
    int bh = blockIdx.y;
    int i0 = blockIdx.x * 64;
    int b = bh >> 4, h = bh & 15;
    int tid = threadIdx.x, tx = tid & 15, ty = tid >> 4;
    const float* pb = p + (size_t)bh * MEMN * TOTAL;
    const float* vb = v + (size_t)bh * TOTAL * HD;
    float acc[4][8] = {};

    for (int j0 = 0; j0 < TOTAL; j0 += 32) {
        for (int t = tid; t < 64 * 8; t += 256) {
            int r = t >> 3;
            int c4 = (t & 7) * 4;
            float4 a = *(const float4*)&pb[(size_t)(i0 + r) * TOTAL + j0 + c4];
            Ps[c4 + 0][r] = a.x; Ps[c4 + 1][r] = a.y;
            Ps[c4 + 2][r] = a.z; Ps[c4 + 3][r] = a.w;
        }
        for (int t = tid; t < 32 * 32; t += 256) {
            int r = t >> 5;
            int c4 = (t & 31) * 4;
            *(float4*)&Vs[r][c4] = *(const float4*)&vb[(size_t)(j0 + r) * HD + c4];
        }
        __syncthreads();
        #pragma unroll
        for (int j = 0; j < 32; j++) {
            float4 a = *(const float4*)&Ps[j][ty * 4];
            float ar[4] = {a.x, a.y, a.z, a.w};
            float4 b0 = *(const float4*)&Vs[j][tx * 8];
            float4 b1 = *(const float4*)&Vs[j][tx * 8 + 4];
            float br[8] = {b0.x, b0.y, b0.z, b0.w, b1.x, b1.y, b1.z, b1.w};
            #pragma unroll
            for (int i = 0; i < 4; i++)
                #pragma unroll
                for (int jc = 0; jc < 8; jc++)
                    acc[i][jc] += ar[i] * br[jc];
        }
        __syncthreads();
    }
    #pragma unroll
    for (int i = 0; i < 4; i++) {
        size_t row = (size_t)b * SEQN + (size_t)chunk * MEMN + i0 + ty * 4 + i;
        float4 o0 = make_float4(acc[i][0], acc[i][1], acc[i][2], acc[i][3]);
        float4 o1 = make_float4(acc[i][4], acc[i][5], acc[i][6], acc[i][7]);
        *(float4*)&y[row * DIMN + h * HD + tx * 8]     = o0;
        *(float4*)&y[row * DIMN + h * HD + tx * 8 + 4] = o1;
    }
}

// ---------------- host orchestration ----------------------------------------
static void launch_gemm_s(const float* A, const unsigned* Bp, float* C,
                          int M, int N, int K, int lda, cudaStream_t st)
{
    dim3 grid(N / GBN, M / GBM);
    gemm_tf32x3_pw<<<grid, 256, GEMM_SMEM, st>>>(A, Bp, C, M, N, K, lda);
}

static void launch_presplit(unsigned* dst, const float* src, int K, int N,
                            int nt_off, int ntiles_tot)
{
    int total4 = (K * N) / 4;
    presplit_kernel<<<(total4 + 255) / 256, 256>>>(dst, src, K, N, nt_off, ntiles_tot);
}

extern "C" void kernel_launch(void* const* d_in, const int* in_sizes, int n_in,
                              void* d_out, int out_size)
{
    (void)in_sizes; (void)n_in; (void)out_size;
    const float* x   = (const float*)d_in[0];
    const float* fc  = (const float*)d_in[1];
    const float* fs  = (const float*)d_in[2];
    const float* om0 = (const float*)d_in[3];
    const float* wq  = (const float*)d_in[4];
    const float* wk  = (const float*)d_in[5];
    const float* wv  = (const float*)d_in[6];
    const float* wo  = (const float*)d_in[7];
    /* d_in[8] = wqm: unused */
    const float* wkm = (const float*)d_in[9];
    const float* wvm = (const float*)d_in[10];
    const float* wm  = (const float*)d_in[11];
    const float* ffw = (const float*)d_in[12];
    const float* w1  = (const float*)d_in[13];
    const float* w2  = (const float*)d_in[14];
    const float* w3  = (const float*)d_in[15];
    const float* mnw = (const float*)d_in[16];
    float* out = (float*)d_out;

    static int configured = 0;
    static cudaStream_t s1;
    static cudaEvent_t evF, evK, evJ;
    if (!configured) {
        cudaFuncSetAttribute(gemm_tf32x3_pw,
                             cudaFuncAttributeMaxDynamicSharedMemorySize,
                             GEMM_SMEM);
        cudaStreamCreateWithFlags(&s1, cudaStreamNonBlocking);
        cudaEventCreateWithFlags(&evF, cudaEventDisableTiming);
        cudaEventCreateWithFlags(&evK, cudaEventDisableTiming);
        cudaEventCreateWithFlags(&evJ, cudaEventDisableTiming);
        configured = 1;
    }
    cudaStream_t s0 = 0;   // default (captured) stream

    float *om, *sx, *om2, *h, *g13, *om4, *mkv, *xqkv, *q, *k, *v, *s, *y;
    cudaGetSymbolAddress((void**)&om,   g_om);
    cudaGetSymbolAddress((void**)&sx,   g_sx);
    cudaGetSymbolAddress((void**)&om2,  g_om2);
    cudaGetSymbolAddress((void**)&h,    g_h);
    cudaGetSymbolAddress((void**)&g13,  g_g13);
    cudaGetSymbolAddress((void**)&om4,  g_om4);
    cudaGetSymbolAddress((void**)&mkv,  g_mkv);
    cudaGetSymbolAddress((void**)&xqkv, g_xqkv);
    cudaGetSymbolAddress((void**)&q,    g_q);
    cudaGetSymbolAddress((void**)&k,    g_k);
    cudaGetSymbolAddress((void**)&v,    g_v);
    cudaGetSymbolAddress((void**)&s,    g_s);
    cudaGetSymbolAddress((void**)&y,    g_y);

    unsigned *pwm, *pwo, *pw2, *pqkv, *pkvm, *pw13;
    cudaGetSymbolAddress((void**)&pwm,  g_p_wm);
    cudaGetSymbolAddress((void**)&pwo,  g_p_wo);
    cudaGetSymbolAddress((void**)&pw2,  g_p_w2);
    cudaGetSymbolAddress((void**)&pqkv, g_p_qkv);
    cudaGetSymbolAddress((void**)&pkvm, g_p_kvm);
    cudaGetSymbolAddress((void**)&pw13, g_p_w13);

    // pre-split + pre-swizzle all weights once per launch (s0)
    launch_presplit(pwm,  wm,  DIMN, DIMN, 0, 16);
    launch_presplit(pwo,  wo,  DIMN, DIMN, 0, 16);
    launch_presplit(pw2,  w2,  HID,  DIMN, 0, 16);
    launch_presplit(pqkv, wq,  DIMN, DIMN, 0,  48);
    launch_presplit(pqkv, wk,  DIMN, DIMN, 16, 48);
    launch_presplit(pqkv, wv,  DIMN, DIMN, 32, 48);
    launch_presplit(pkvm, wkm, DIMN, DIMN, 0,  32);
    launch_presplit(pkvm, wvm, DIMN, DIMN, 16, 32);
    launch_presplit(pw13, w1,  DIMN, HID,  0,  88);
    launch_presplit(pw13, w3,  DIMN, HID,  44, 88);

    const float scale = 0.08838834764831845f;   // 1/sqrt(128)

    for (int c = 0; c < NCHUNK; c++) {
        const float* omp;
        if (c == 0) {
            omp = om0;
        } else {
            gather_rows<<<RROWS, 256, 0, s0>>>(om, y, c - 1);
            omp = om;
        }
        gather_rows<<<RROWS, 256, 0, s0>>>(sx, x, c);

        // fork: qkv projection + build_q on s1 (independent of FFN chain)
        cudaEventRecord(evF, s0);
        cudaStreamWaitEvent(s1, evF, 0);
        launch_gemm_s(sx, pqkv, xqkv, RROWS, 3 * DIMN, DIMN, DIMN, s1);
        cudaEventRecord(evK, s1);          // xqkv ready
        build_q_kernel<<<(BATCH * MEMN * NH * 64 + 255) / 256, 256, 0, s1>>>(
            xqkv, fc, fs, q);
        cudaEventRecord(evJ, s1);          // q ready

        // s0: memory-stream FFN chain
        launch_gemm_s(omp, pwm, om2, RROWS, DIMN, DIMN, DIMN, s0);
        rmsnorm_kernel<<<RROWS, 256, 0, s0>>>(h, om2, ffw);
        launch_gemm_s(h, pw13, g13, RROWS, 2 * HID, DIMN, DIMN, s0);
        silu_mul_kernel<<<(RROWS * HID / 4 + 255) / 256, 256, 0, s0>>>(g13);
        launch_gemm_s(g13, pw2, h, RROWS, DIMN, HID, 2 * HID, s0);
        add_rmsnorm_kernel<<<RROWS, 256, 0, s0>>>(om4, om2, h, mnw);
        launch_gemm_s(om4, pkvm, mkv, RROWS, 2 * DIMN, DIMN, DIMN, s0);

        // join 1: build_kv needs xqkv (s1) + mkv (s0)
        cudaStreamWaitEvent(s0, evK, 0);
        build_kv_kernel<<<(BATCH * TOTAL * NH * 64 + 255) / 256, 256, 0, s0>>>(
            mkv, xqkv, fc, fs, k, v);

        // join 2: qk needs q (s1)
        cudaStreamWaitEvent(s0, evJ, 0);
        {
            dim3 g(2, BATCH * NH);
            qk_softmax_kernel<<<g, 256, 0, s0>>>(q, k, s, scale);
        }
        {
            dim3 g(2, BATCH * NH);
            pv_kernel<<<g, 256, 0, s0>>>(s, v, y, c);
        }
    }

    // final projection: out = y @ wo (s0)
    launch_gemm_s(y, pwo, out, BATCH * SEQN, DIMN, DIMN, DIMN, s0);
}

// round 16
// speedup vs baseline: 1.1851x; 1.0193x over previous
#include <cuda_runtime.h>
#include <math.h>

#define DIMN 2048
#define NH 16
#define HD 128
#define MEMN 128
#define SEQN 2048
#define BATCH 4
#define HID 5632
#define NCHUNK (SEQN / MEMN)     // 16
#define RROWS (BATCH * MEMN)     // 512 rows per step
#define TOTAL (2 * MEMN)         // 256
#define EPS 1e-5f

// ---------------- scratch (__device__ globals; no allocation) ----------------
__device__ float g_om2 [RROWS * DIMN];
__device__ float g_h   [RROWS * DIMN];        // rmsnorm out / FFN out
__device__ float g_g13 [RROWS * 2 * HID];     // fused w1|w3 output
__device__ float g_om4 [RROWS * DIMN];
__device__ float g_mkv [RROWS * 2 * DIMN];    // fused mk|mv
__device__ float g_xqkv_all[(size_t)BATCH * SEQN * 3 * DIMN];  // all chunks upfront
__device__ float g_k  [BATCH * NH * TOTAL * HD];
__device__ float g_v  [BATCH * NH * TOTAL * HD];
__device__ float g_s  [BATCH * NH * MEMN * TOTAL];
__device__ float g_y  [BATCH * SEQN * DIMN];

// pre-split + pre-swizzled weights (hi/lo interleaved, GEMM B-tile layout)
__device__ unsigned g_p_wm  [DIMN * DIMN * 2];
__device__ unsigned g_p_wo  [DIMN * DIMN * 2];
__device__ unsigned g_p_w2  [HID  * DIMN * 2];
__device__ unsigned g_p_qkv [DIMN * 3 * DIMN * 2];   // wq | wk | wv
__device__ unsigned g_p_kvm [DIMN * 2 * DIMN * 2];   // wkm | wvm
__device__ unsigned g_p_w13 [DIMN * 2 * HID  * 2];   // w1 | w3

// ---------------- reductions ----------------
__device__ __forceinline__ float block_sum256(float v) {
    __shared__ float sh[8];
    #pragma unroll
    for (int o = 16; o > 0; o >>= 1) v += __shfl_xor_sync(0xffffffffu, v, o);
    if ((threadIdx.x & 31) == 0) sh[threadIdx.x >> 5] = v;
    __syncthreads();
    float t = 0.f;
    if (threadIdx.x < 32) {
        t = (threadIdx.x < 8) ? sh[threadIdx.x] : 0.f;
        #pragma unroll
        for (int o = 4; o > 0; o >>= 1) t += __shfl_xor_sync(0xffffffffu, t, o);
        if (threadIdx.x == 0) sh[0] = t;
    }
    __syncthreads();
    float r = sh[0];
    __syncthreads();
    return r;
}

// ---------------- tf32 helpers ----------------
__device__ __forceinline__ unsigned f2tf32(float f) {
    unsigned u;
    asm("cvt.rna.tf32.f32 %0, %1;" : "=r"(u) : "f"(f));
    return u;
}

__device__ __forceinline__ void split_tf32(float f, unsigned& hi, unsigned& lo) {
    hi = f2tf32(f);
    lo = f2tf32(f - __uint_as_float(hi));
}

__device__ __forceinline__ void mma_tf32(float c[4], const unsigned a[4], const unsigned b[2]) {
    asm volatile(
        "mma.sync.aligned.m16n8k8.row.col.f32.tf32.tf32.f32 "
        "{%0,%1,%2,%3}, {%4,%5,%6,%7}, {%8,%9}, {%0,%1,%2,%3};"
        : "+f"(c[0]), "+f"(c[1]), "+f"(c[2]), "+f"(c[3])
        : "r"(a[0]), "r"(a[1]), "r"(a[2]), "r"(a[3]), "r"(b[0]), "r"(b[1]));
}

// ---------------- weight pre-split into a concatenated-N layout -------------
__global__ void __launch_bounds__(256) presplit_kernel(
    unsigned* __restrict__ dst, const float* __restrict__ src,
    int K, int N, int nt_off, int ntiles_tot)
{
    int idx = blockIdx.x * 256 + threadIdx.x;   // one float4 per thread
    int total = (K * N) >> 2;
    if (idx >= total) return;
    int nrow4 = N >> 2;
    int k  = idx / nrow4;
    int nn = (idx - k * nrow4) << 2;
    float4 v = ((const float4*)src)[idx];
    int kt = k >> 5, kr = k & 31;
    int nt = nn >> 7, nl = nn & 127;
    int nc = nl ^ ((kr & 3) * 8);
    size_t base = (((size_t)kt * ntiles_tot + nt_off + nt) << 13)
                + ((size_t)kr * 128 + nc) * 2;
    unsigned h0, l0, h1, l1, h2, l2, h3, l3;
    split_tf32(v.x, h0, l0);
    split_tf32(v.y, h1, l1);
    split_tf32(v.z, h2, l2);
    split_tf32(v.w, h3, l3);
    *(uint4*)&dst[base]     = make_uint4(h0, l0, h1, l1);
    *(uint4*)&dst[base + 4] = make_uint4(h2, l2, h3, l3);
}

// ---------------- narrow GEMM (BN=128, 2 CTA/SM), grouped-row A --------------
// A row r lives at A + (r>>7)*gstride + (r&127)*lda.
// For contiguous A pass gstride = 128*lda. For chunk slices of y pass
// gstride = SEQN*DIMN. Per-output math identical to R12/R14.
#define GBM 64
#define GBN 128
#define GBK 32
#define A_BUF_WORDS (GBM * GBK * 2)    // 16KB/stage
#define B_BUF_WORDS (GBK * GBN * 2)    // 32KB/stage
#define GEMM_SMEM ((2 * A_BUF_WORDS + 2 * B_BUF_WORDS) * 4)   // 98304 B

__global__ void __launch_bounds__(256) gemm_tf32x3_pw(
    const float* __restrict__ A, const unsigned* __restrict__ Bp,
    float* __restrict__ C, int M, int N, int K, int lda, size_t gstride)
{
    extern __shared__ unsigned su[];
    typedef unsigned ABuf[GBM][GBK][2];
    typedef unsigned BBuf[GBK][GBN][2];
    ABuf* As = (ABuf*)su;
    BBuf* Bs = (BBuf*)(su + 2 * A_BUF_WORDS);

    const int tid  = threadIdx.x;
    const int lane = tid & 31;
    const int wid  = tid >> 5;
    const int warp_m = wid & 1;
    const int warp_n = wid >> 1;
    const int row0 = blockIdx.y * GBM;
    const int col0 = blockIdx.x * GBN;
    const int ntiles = N >> 7;

    unsigned sbB[2];
    sbB[0] = (unsigned)__cvta_generic_to_shared(&Bs[0][0][0][0]);
    sbB[1] = (unsigned)__cvta_generic_to_shared(&Bs[1][0][0][0]);

    float4 ra[2];
    float acc[2][4][4];
    #pragma unroll
    for (int i = 0; i < 2; i++)
        #pragma unroll
        for (int j = 0; j < 4; j++)
            #pragma unroll
            for (int l = 0; l < 4; l++) acc[i][j][l] = 0.f;

    {
        const unsigned* btile = Bp + (((size_t)0 * ntiles + (col0 >> 7)) << 13);
        #pragma unroll
        for (int i = 0; i < 8; i++) {
            unsigned d = sbB[0] + (unsigned)(tid + i * 256) * 16u;
            const unsigned* g = btile + (size_t)(tid + i * 256) * 4;
            asm volatile("cp.async.cg.shared.global [%0], [%1], 16;\n"
                         :: "r"(d), "l"(g));
        }
        asm volatile("cp.async.commit_group;\n");
    }
    #pragma unroll
    for (int i = 0; i < 2; i++) {
        int idx = tid + i * 256;
        int m = idx >> 3, k4 = idx & 7;
        int r = row0 + m;
        ra[i] = *(const float4*)&A[(size_t)(r >> 7) * gstride
                                   + (size_t)(r & 127) * lda + k4 * 4];
    }
    #pragma unroll
    for (int i = 0; i < 2; i++) {
        int idx = tid + i * 256;
        int m = idx >> 3, k4 = idx & 7;
        int kc = (k4 * 4) ^ ((m & 7) * 4);
        unsigned h0, l0, h1, l1, h2, l2, h3, l3;
        split_tf32(ra[i].x, h0, l0);
        split_tf32(ra[i].y, h1, l1);
        split_tf32(ra[i].z, h2, l2);
        split_tf32(ra[i].w, h3, l3);
        *(uint4*)&As[0][m][kc][0]     = make_uint4(h0, l0, h1, l1);
        *(uint4*)&As[0][m][kc + 2][0] = make_uint4(h2, l2, h3, l3);
    }
    asm volatile("cp.async.wait_group 0;\n" ::: "memory");
    __syncthreads();

    int buf = 0;
    for (int kk = 0; kk < K; kk += GBK) {
        const int nxt = buf ^ 1;
        const bool more = (kk + GBK < K);

        if (more) {
            const unsigned* btile = Bp
                + (((size_t)((kk + GBK) >> 5) * ntiles + (col0 >> 7)) << 13);
            #pragma unroll
            for (int i = 0; i < 8; i++) {
                unsigned d = sbB[nxt] + (unsigned)(tid + i * 256) * 16u;
                const unsigned* g = btile + (size_t)(tid + i * 256) * 4;
                asm volatile("cp.async.cg.shared.global [%0], [%1], 16;\n"
                             :: "r"(d), "l"(g));
            }
            asm volatile("cp.async.commit_group;\n");
            #pragma unroll
            for (int i = 0; i < 2; i++) {
                int idx = tid + i * 256;
                int m = idx >> 3, k4 = idx & 7;
                int r = row0 + m;
                ra[i] = *(const float4*)&A[(size_t)(r >> 7) * gstride
                                           + (size_t)(r & 127) * lda
                                           + kk + GBK + k4 * 4];
            }
        }

        #pragma unroll
        for (int ks = 0; ks < 4; ks++) {
            int kq = ks * 8 + (lane & 3);
            int swb = (lane & 3) * 8;
            unsigned afH[2][4], afL[2][4];
            unsigned bfH[4][2], bfL[4][2];
            #pragma unroll
            for (int mf = 0; mf < 2; mf++) {
                int m  = warp_m * 32 + mf * 16 + (lane >> 2);
                int sw = (lane >> 2) * 4;
                uint2 a0 = *(const uint2*)&As[buf][m][kq ^ sw][0];
                uint2 a1 = *(const uint2*)&As[buf][m + 8][kq ^ sw][0];
                uint2 a2 = *(const uint2*)&As[buf][m][(kq + 4) ^ sw][0];
                uint2 a3 = *(const uint2*)&As[buf][m + 8][(kq + 4) ^ sw][0];
                afH[mf][0] = a0.x; afL[mf][0] = a0.y;
                afH[mf][1] = a1.x; afL[mf][1] = a1.y;
                afH[mf][2] = a2.x; afL[mf][2] = a2.y;
                afH[mf][3] = a3.x; afL[mf][3] = a3.y;
            }
            #pragma unroll
            for (int nf = 0; nf < 4; nf++) {
                int n = warp_n * 32 + nf * 8 + (lane >> 2);
                uint2 b0 = *(const uint2*)&Bs[buf][kq][n ^ swb][0];
                uint2 b1 = *(const uint2*)&Bs[buf][kq + 4][n ^ swb][0];
                bfH[nf][0] = b0.x; bfL[nf][0] = b0.y;
                bfH[nf][1] = b1.x; bfL[nf][1] = b1.y;
            }
            #pragma unroll
            for (int mf = 0; mf < 2; mf++)
                #pragma unroll
                for (int nf = 0; nf < 4; nf++) {
                    mma_tf32(acc[mf][nf], afL[mf], bfH[nf]);
                    mma_tf32(acc[mf][nf], afH[mf], bfL[nf]);
                    mma_tf32(acc[mf][nf], afH[mf], bfH[nf]);
                }
        }

        if (more) {
            #pragma unroll
            for (int i = 0; i < 2; i++) {
                int idx = tid + i * 256;
                int m = idx >> 3, k4 = idx & 7;
                int kc = (k4 * 4) ^ ((m & 7) * 4);
                unsigned h0, l0, h1, l1, h2, l2, h3, l3;
                split_tf32(ra[i].x, h0, l0);
                split_tf32(ra[i].y, h1, l1);
                split_tf32(ra[i].z, h2, l2);
                split_tf32(ra[i].w, h3, l3);
                *(uint4*)&As[nxt][m][kc][0]     = make_uint4(h0, l0, h1, l1);
                *(uint4*)&As[nxt][m][kc + 2][0] = make_uint4(h2, l2, h3, l3);
            }
            asm volatile("cp.async.wait_group 0;\n" ::: "memory");
        }
        __syncthreads();
        buf = nxt;
    }

    #pragma unroll
    for (int mf = 0; mf < 2; mf++) {
        int row = row0 + warp_m * 32 + mf * 16 + (lane >> 2);
        #pragma unroll
        for (int nf = 0; nf < 4; nf++) {
            int col = col0 + warp_n * 32 + nf * 8 + 2 * (lane & 3);
            *(float2*)&C[(size_t)row * N + col] =
                make_float2(acc[mf][nf][0], acc[mf][nf][1]);
            *(float2*)&C[(size_t)(row + 8) * N + col] =
                make_float2(acc[mf][nf][2], acc[mf][nf][3]);
        }
    }
}

// ---------------- rmsnorm ----------------------------------------------------
__global__ void __launch_bounds__(256) rmsnorm_kernel(
    float* __restrict__ out, const float* __restrict__ in, const float* __restrict__ w)
{
    int row = blockIdx.x;
    const float* xr = in + (size_t)row * DIMN;
    float vals[8];
    float ss = 0.f;
    #pragma unroll
    for (int t = 0; t < 8; t++) {
        float v = xr[threadIdx.x + t * 256];
        vals[t] = v; ss += v * v;
    }
    float tot = block_sum256(ss);
    float sc = rsqrtf(tot * (1.0f / DIMN) + EPS);
    #pragma unroll
    for (int t = 0; t < 8; t++)
        out[(size_t)row * DIMN + threadIdx.x + t * 256] =
            vals[t] * sc * w[threadIdx.x + t * 256];
}

__global__ void __launch_bounds__(256) add_rmsnorm_kernel(
    float* __restrict__ out, const float* __restrict__ a,
    const float* __restrict__ b, const float* __restrict__ w)
{
    int row = blockIdx.x;
    const float* ar = a + (size_t)row * DIMN;
    const float* br = b + (size_t)row * DIMN;
    float vals[8];
    float ss = 0.f;
    #pragma unroll
    for (int t = 0; t < 8; t++) {
        float v = ar[threadIdx.x + t * 256] + br[threadIdx.x + t * 256];
        vals[t] = v; ss += v * v;
    }
    float tot = block_sum256(ss);
    float sc = rsqrtf(tot * (1.0f / DIMN) + EPS);
    #pragma unroll
    for (int t = 0; t < 8; t++)
        out[(size_t)row * DIMN + threadIdx.x + t * 256] =
            vals[t] * sc * w[threadIdx.x + t * 256];
}

// ---------------- fused-buffer silu: g13[:, :HID] = silu(g1) * g3 -----------
__global__ void __launch_bounds__(256) silu_mul_kernel(float* __restrict__ g13)
{
    int idx = blockIdx.x * 256 + threadIdx.x;
    int n4 = RROWS * HID / 4;
    if (idx >= n4) return;
    int row = idx / (HID / 4);
    int c4  = idx - row * (HID / 4);
    float4* ap = (float4*)&g13[(size_t)row * 2 * HID + c4 * 4];
    float4 av = *ap;
    float4 bv = *(const float4*)&g13[(size_t)row * 2 * HID + HID + c4 * 4];
    av.x = av.x / (1.f + expf(-av.x)) * bv.x;
    av.y = av.y / (1.f + expf(-av.y)) * bv.y;
    av.z = av.z / (1.f + expf(-av.z)) * bv.z;
    av.w = av.w / (1.f + expf(-av.w)) * bv.w;
    *ap = av;
}

// ---------------- build K,V (mkv + xqkv_all chunk slice) with RoPE on K -----
__global__ void __launch_bounds__(256) build_kv_kernel(
    const float* __restrict__ mkv, const float* __restrict__ xqkv_all,
    const float* __restrict__ fc, const float* __restrict__ fs,
    float* __restrict__ k, float* __restrict__ v, int chunk)
{
    int idx = blockIdx.x * 256 + threadIdx.x;
    if (idx >= BATCH * TOTAL * NH * (HD / 2)) return;
    int j   = idx & 63;
    int h   = (idx >> 6) & 15;
    int pos = (idx >> 10) & 255;
    int b   = idx >> 18;
    int col = h * HD + 2 * j;
    const float *sk, *sv;
    if (pos < MEMN) {
        size_t r = (size_t)(b * MEMN + pos) * (2 * DIMN);
        sk = mkv + r + col;
        sv = mkv + r + DIMN + col;
    } else {
        size_t r = (size_t)(b * SEQN + chunk * MEMN + pos - MEMN) * (3 * DIMN);
        sk = xqkv_all + r + DIMN + col;
        sv = xqkv_all + r + 2 * DIMN + col;
    }
    float c = fc[pos * 64 + j], s = fs[pos * 64 + j];
    float kr = sk[0], ki = sk[1];
    size_t o = ((size_t)(b * NH + h) * TOTAL + pos) * HD + 2 * j;
    k[o]     = kr * c - ki * s;
    k[o + 1] = kr * s + ki * c;
    v[o]     = sv[0];
    v[o + 1] = sv[1];
}

// ---------------- fused qk + causal softmax (RoPE on Q load) -----------------
// Q read directly from xqkv_all (xq slice), RoPE applied during the smem fill
// with the exact expressions build_q used -> bit-identical Q values.
__global__ void __launch_bounds__(256) qk_softmax_kernel(
    const float* __restrict__ xqkv_all, const float* __restrict__ k,
    const float* __restrict__ fc, const float* __restrict__ fs,
    float* __restrict__ s, float scale, int chunk)
{
    __shared__ float Qs[64][64];
    __shared__ float Ks[64][64];
    int bh = blockIdx.y;
    int b = bh >> 4, h = bh & 15;
    int i0 = blockIdx.x * 64;
    int tid = threadIdx.x, tx = tid & 15, ty = tid >> 4;
    const float* qbase = xqkv_all
        + (size_t)(b * SEQN + chunk * MEMN) * (3 * DIMN) + h * HD;
    const float* kb = k + (size_t)bh * TOTAL * HD;

    float acc[4][16];
    #pragma unroll
    for (int r = 0; r < 4; r++)
        #pragma unroll
        for (int c = 0; c < 16; c++) acc[r][c] = 0.f;

    for (int dc = 0; dc < HD; dc += 64) {
        for (int t = tid; t < 64 * 16; t += 256) {
            int r = t >> 4;
            int c4 = (t & 15) * 4;
            float4 a = *(const float4*)&qbase[(size_t)(i0 + r) * (3 * DIMN) + dc + c4];
            int pos = MEMN + i0 + r;
            int j = (dc + c4) >> 1;
            float c0 = fc[pos * 64 + j],     s0 = fs[pos * 64 + j];
            float c1 = fc[pos * 64 + j + 1], s1 = fs[pos * 64 + j + 1];
            Qs[c4 + 0][r] = a.x * c0 - a.y * s0;
            Qs[c4 + 1][r] = a.x * s0 + a.y * c0;
            Qs[c4 + 2][r] = a.z * c1 - a.w * s1;
            Qs[c4 + 3][r] = a.z * s1 + a.w * c1;
        }
        for (int jt = 0; jt < 4; jt++) {
            __syncthreads();
            for (int t = tid; t < 64 * 16; t += 256) {
                int r = t >> 4;
                int c4 = (t & 15) * 4;
                float4 bvec = *(const float4*)&kb[(size_t)(jt * 64 + r) * HD + dc + c4];
                Ks[c4 + 0][r] = bvec.x; Ks[c4 + 1][r] = bvec.y;
                Ks[c4 + 2][r] = bvec.z; Ks[c4 + 3][r] = bvec.w;
            }
            __syncthreads();
            #pragma unroll
            for (int d = 0; d < 64; d++) {
                float4 a = *(const float4*)&Qs[d][ty * 4];
                float4 bvec = *(const float4*)&Ks[d][tx * 4];
                float ar[4] = {a.x, a.y, a.z, a.w};
                float br[4] = {bvec.x, bvec.y, bvec.z, bvec.w};
                #pragma unroll
                for (int r = 0; r < 4; r++)
                    #pragma unroll
                    for (int jc = 0; jc < 4; jc++)
                        acc[r][jt * 4 + jc] += ar[r] * br[jc];
            }
        }
        __syncthreads();
    }

    float sum[4];
    #pragma unroll
    for (int r = 0; r < 4; r++) {
        int ig = i0 + ty * 4 + r;
        int limit = MEMN + ig;
        float ml = -3.4e38f;
        #pragma unroll
        for (int c = 0; c < 16; c++) {
            int j = (c >> 2) * 64 + tx * 4 + (c & 3);
            acc[r][c] = (j <= limit) ? acc[r][c] * scale : -3.4e38f;
            ml = fmaxf(ml, acc[r][c]);
        }
        #pragma unroll
        for (int o = 8; o > 0; o >>= 1)
            ml = fmaxf(ml, __shfl_xor_sync(0xffffffffu, ml, o));
        float sl = 0.f;
        #pragma unroll
        for (int c = 0; c < 16; c++) {
            float e = expf(acc[r][c] - ml);
            acc[r][c] = e;
            sl += e;
        }
        #pragma unroll
        for (int o = 8; o > 0; o >>= 1)
            sl += __shfl_xor_sync(0xffffffffu, sl, o);
        sum[r] = sl;
    }

    #pragma unroll
    for (int r = 0; r < 4; r++) {
        int ig = i0 + ty * 4 + r;
        float inv = 1.f / sum[r];
        #pragma unroll
        for (int jt = 0; jt < 4; jt++) {
            float4 o = make_float4(acc[r][jt * 4 + 0] * inv,
                                   acc[r][jt * 4 + 1] * inv,
                                   acc[r][jt * 4 + 2] * inv,
                                   acc[r][jt * 4 + 3] * inv);
            *(float4*)&s[((size_t)bh * MEMN + ig) * TOTAL + jt * 64 + tx * 4] = o;
        }
    }
}

// ---------------- O = P@V -> y chunk -----------------------------------------
__global__ void __launch_bounds__(256) pv_kernel(
    const float* __restrict__ p, const float* __restrict__ v,
    float* __restrict__ y, int chunk)
{
    __shared__ float Ps[32][64];
    __shared__ float Vs[32][128];
    int bh = blockIdx.y;
    int i0 = blockIdx.x * 64;
    int b = bh >> 4, h = bh & 15;
    int tid = threadIdx.x, tx = tid & 15, ty = tid >> 4;
    const float* pb = p + (size_t)bh * MEMN * TOTAL;
    const float* vb = v + (size_t)bh * TOTAL * HD;
    float acc[4][8] = {};

    for (int j0 = 0; j0 < TOTAL; j0 += 32) {
        for (int t = tid; t < 64 * 8; t += 256) {
            int r = t >> 3;
            int c4 = (t & 7) * 4;
            float4 a = *(const float4*)&pb[(size_t)(i0 + r) * TOTAL + j0 + c4];
            Ps[c4 + 0][r] = a.x; Ps[c4 + 1][r] = a.y;
            Ps[c4 + 2][r] = a.z; Ps[c4 + 3][r] = a.w;
        }
        for (int t = tid; t < 32 * 32; t += 256) {
            int r = t >> 5;
            int c4 = (t & 31) * 4;
            *(float4*)&Vs[r][c4] = *(const float4*)&vb[(size_t)(j0 + r) * HD + c4];
        }
        __syncthreads();
        #pragma unroll
        for (int j = 0; j < 32; j++) {
            float4 a = *(const float4*)&Ps[j][ty * 4];
            float ar[4] = {a.x, a.y, a.z, a.w};
            float4 b0 = *(const float4*)&Vs[j][tx * 8];
            float4 b1 = *(const float4*)&Vs[j][tx * 8 + 4];
            float br[8] = {b0.x, b0.y, b0.z, b0.w, b1.x, b1.y, b1.z, b1.w};
            #pragma unroll
            for (int i = 0; i < 4; i++)
                #pragma unroll
                for (int jc = 0; jc < 8; jc++)
                    acc[i][jc] += ar[i] * br[jc];
        }
        __syncthreads();
    }
    #pragma unroll
    for (int i = 0; i < 4; i++) {
        size_t row = (size_t)b * SEQN + (size_t)chunk * MEMN + i0 + ty * 4 + i;
        float4 o0 = make_float4(acc[i][0], acc[i][1], acc[i][2], acc[i][3]);
        float4 o1 = make_float4(acc[i][4], acc[i][5], acc[i][6], acc[i][7]);
        *(float4*)&y[row * DIMN + h * HD + tx * 8]     = o0;
        *(float4*)&y[row * DIMN + h * HD + tx * 8 + 4] = o1;
    }
}

// ---------------- host orchestration ----------------------------------------
static void launch_gemm(const float* A, const unsigned* Bp, float* C,
                        int M, int N, int K, int lda, size_t gstride)
{
    dim3 grid(N / GBN, M / GBM);
    gemm_tf32x3_pw<<<grid, 256, GEMM_SMEM>>>(A, Bp, C, M, N, K, lda, gstride);
}

static void launch_presplit(unsigned* dst, const float* src, int K, int N,
                            int nt_off, int ntiles_tot)
{
    int total4 = (K * N) / 4;
    presplit_kernel<<<(total4 + 255) / 256, 256>>>(dst, src, K, N, nt_off, ntiles_tot);
}

extern "C" void kernel_launch(void* const* d_in, const int* in_sizes, int n_in,
                              void* d_out, int out_size)
{
    (void)in_sizes; (void)n_in; (void)out_size;
    const float* x   = (const float*)d_in[0];
    const float* fc  = (const float*)d_in[1];
    const float* fs  = (const float*)d_in[2];
    const float* om0 = (const float*)d_in[3];
    const float* wq  = (const float*)d_in[4];
    const float* wk  = (const float*)d_in[5];
    const float* wv  = (const float*)d_in[6];
    const float* wo  = (const float*)d_in[7];
    /* d_in[8] = wqm: unused */
    const float* wkm = (const float*)d_in[9];
    const float* wvm = (const float*)d_in[10];
    const float* wm  = (const float*)d_in[11];
    const float* ffw = (const float*)d_in[12];
    const float* w1  = (const float*)d_in[13];
    const float* w2  = (const float*)d_in[14];
    const float* w3  = (const float*)d_in[15];
    const float* mnw = (const float*)d_in[16];
    float* out = (float*)d_out;

    static int configured = 0;
    if (!configured) {
        cudaFuncSetAttribute(gemm_tf32x3_pw,
                             cudaFuncAttributeMaxDynamicSharedMemorySize,
                             GEMM_SMEM);
        configured = 1;
    }

    float *om2, *h, *g13, *om4, *mkv, *xqkv, *k, *v, *s, *y;
    cudaGetSymbolAddress((void**)&om2,  g_om2);
    cudaGetSymbolAddress((void**)&h,    g_h);
    cudaGetSymbolAddress((void**)&g13,  g_g13);
    cudaGetSymbolAddress((void**)&om4,  g_om4);
    cudaGetSymbolAddress((void**)&mkv,  g_mkv);
    cudaGetSymbolAddress((void**)&xqkv, g_xqkv_all);
    cudaGetSymbolAddress((void**)&k,    g_k);
    cudaGetSymbolAddress((void**)&v,    g_v);
    cudaGetSymbolAddress((void**)&s,    g_s);
    cudaGetSymbolAddress((void**)&y,    g_y);

    unsigned *pwm, *pwo, *pw2, *pqkv, *pkvm, *pw13;
    cudaGetSymbolAddress((void**)&pwm,  g_p_wm);
    cudaGetSymbolAddress((void**)&pwo,  g_p_wo);
    cudaGetSymbolAddress((void**)&pw2,  g_p_w2);
    cudaGetSymbolAddress((void**)&pqkv, g_p_qkv);
    cudaGetSymbolAddress((void**)&pkvm, g_p_kvm);
    cudaGetSymbolAddress((void**)&pw13, g_p_w13);

    // pre-split + pre-swizzle all weights once per launch
    launch_presplit(pwm,  wm,  DIMN, DIMN, 0, 16);
    launch_presplit(pwo,  wo,  DIMN, DIMN, 0, 16);
    launch_presplit(pw2,  w2,  HID,  DIMN, 0, 16);
    launch_presplit(pqkv, wq,  DIMN, DIMN, 0,  48);
    launch_presplit(pqkv, wk,  DIMN, DIMN, 16, 48);
    launch_presplit(pqkv, wv,  DIMN, DIMN, 32, 48);
    launch_presplit(pkvm, wkm, DIMN, DIMN, 0,  32);
    launch_presplit(pkvm, wvm, DIMN, DIMN, 16, 32);
    launch_presplit(pw13, w1,  DIMN, HID,  0,  88);
    launch_presplit(pw13, w3,  DIMN, HID,  44, 88);

    // ALL chunks' qkv projection in ONE giant GEMM (x rows are contiguous)
    launch_gemm(x, pqkv, xqkv, BATCH * SEQN, 3 * DIMN, DIMN,
                DIMN, (size_t)128 * DIMN);

    const float scale = 0.08838834764831845f;   // 1/sqrt(128)
    const size_t CONT = (size_t)128 * DIMN;         // contiguous gstride (lda=DIMN)
    const size_t CONT13 = (size_t)128 * 2 * HID;    // contiguous gstride (lda=2*HID)

    for (int c = 0; c < NCHUNK; c++) {
        // A for wm: previous chunk's attention output rows inside y, or om0
        const float* omp   = c ? (y + (size_t)(c - 1) * MEMN * DIMN) : om0;
        size_t       omstr = c ? (size_t)SEQN * DIMN : CONT;

        // memory-stream FFN chain
        launch_gemm(omp, pwm, om2, RROWS, DIMN, DIMN, DIMN, omstr);
        rmsnorm_kernel<<<RROWS, 256>>>(h, om2, ffw);
        launch_gemm(h, pw13, g13, RROWS, 2 * HID, DIMN, DIMN, CONT);
        silu_mul_kernel<<<(RROWS * HID / 4 + 255) / 256, 256>>>(g13);
        launch_gemm(g13, pw2, h, RROWS, DIMN, HID, 2 * HID, CONT13);
        add_rmsnorm_kernel<<<RROWS, 256>>>(om4, om2, h, mnw);
        launch_gemm(om4, pkvm, mkv, RROWS, 2 * DIMN, DIMN, DIMN, CONT);

        // assemble roped k/v; attention
        build_kv_kernel<<<(BATCH * TOTAL * NH * 64 + 255) / 256, 256>>>(
            mkv, xqkv, fc, fs, k, v, c);
        {
            dim3 g(2, BATCH * NH);
            qk_softmax_kernel<<<g, 256>>>(xqkv, k, fc, fs, s, scale, c);
        }
        {
            dim3 g(2, BATCH * NH);
            pv_kernel<<<g, 256>>>(s, v, y, c);
        }
    }

    // final projection: out = y @ wo
    launch_gemm(y, pwo, out, BATCH * SEQN, DIMN, DIMN, DIMN, CONT);
}

// round 17
// speedup vs baseline: 1.2526x; 1.0570x over previous
#include <cuda_runtime.h>
#include <math.h>

#define DIMN 2048
#define NH 16
#define HD 128
#define MEMN 128
#define SEQN 2048
#define BATCH 4
#define HID 5632
#define NCHUNK (SEQN / MEMN)     // 16
#define RROWS (BATCH * MEMN)     // 512 rows per step
#define TOTAL (2 * MEMN)         // 256
#define EPS 1e-5f

// ---------------- scratch (__device__ globals; no allocation) ----------------
__device__ float g_om2 [RROWS * DIMN];
__device__ float g_h   [RROWS * DIMN];        // rmsnorm out / FFN out
__device__ float g_g13 [RROWS * 2 * HID];     // fused w1|w3 output
__device__ float g_om4 [RROWS * DIMN];
__device__ float g_mkv [RROWS * 2 * DIMN];    // fused mk|mv
__device__ float g_xqkv_all[(size_t)BATCH * SEQN * 3 * DIMN];  // all chunks upfront
__device__ float g_k  [BATCH * NH * TOTAL * HD];
__device__ float g_v  [BATCH * NH * TOTAL * HD];
__device__ float g_s  [BATCH * NH * MEMN * TOTAL];
__device__ float g_y  [BATCH * SEQN * DIMN];

// pre-split + pre-swizzled weights (hi/lo interleaved, GEMM B-tile layout)
__device__ unsigned g_p_wm  [DIMN * DIMN * 2];
__device__ unsigned g_p_wo  [DIMN * DIMN * 2];
__device__ unsigned g_p_w2  [HID  * DIMN * 2];
__device__ unsigned g_p_qkv [DIMN * 3 * DIMN * 2];   // wq | wk | wv
__device__ unsigned g_p_kvm [DIMN * 2 * DIMN * 2];   // wkm | wvm
__device__ unsigned g_p_w13 [DIMN * 2 * HID  * 2];   // w1 | w3

// ---------------- reductions ----------------
__device__ __forceinline__ float block_sum256(float v) {
    __shared__ float sh[8];
    #pragma unroll
    for (int o = 16; o > 0; o >>= 1) v += __shfl_xor_sync(0xffffffffu, v, o);
    if ((threadIdx.x & 31) == 0) sh[threadIdx.x >> 5] = v;
    __syncthreads();
    float t = 0.f;
    if (threadIdx.x < 32) {
        t = (threadIdx.x < 8) ? sh[threadIdx.x] : 0.f;
        #pragma unroll
        for (int o = 4; o > 0; o >>= 1) t += __shfl_xor_sync(0xffffffffu, t, o);
        if (threadIdx.x == 0) sh[0] = t;
    }
    __syncthreads();
    float r = sh[0];
    __syncthreads();
    return r;
}

// ---------------- tf32 helpers ----------------
__device__ __forceinline__ unsigned f2tf32(float f) {
    unsigned u;
    asm("cvt.rna.tf32.f32 %0, %1;" : "=r"(u) : "f"(f));
    return u;
}

__device__ __forceinline__ void split_tf32(float f, unsigned& hi, unsigned& lo) {
    hi = f2tf32(f);
    lo = f2tf32(f - __uint_as_float(hi));
}

__device__ __forceinline__ void mma_tf32(float c[4], const unsigned a[4], const unsigned b[2]) {
    asm volatile(
        "mma.sync.aligned.m16n8k8.row.col.f32.tf32.tf32.f32 "
        "{%0,%1,%2,%3}, {%4,%5,%6,%7}, {%8,%9}, {%0,%1,%2,%3};"
        : "+f"(c[0]), "+f"(c[1]), "+f"(c[2]), "+f"(c[3])
        : "r"(a[0]), "r"(a[1]), "r"(a[2]), "r"(a[3]), "r"(b[0]), "r"(b[1]));
}

// ---------------- weight pre-split into a concatenated-N layout -------------
__global__ void __launch_bounds__(256) presplit_kernel(
    unsigned* __restrict__ dst, const float* __restrict__ src,
    int K, int N, int nt_off, int ntiles_tot)
{
    int idx = blockIdx.x * 256 + threadIdx.x;   // one float4 per thread
    int total = (K * N) >> 2;
    if (idx >= total) return;
    int nrow4 = N >> 2;
    int k  = idx / nrow4;
    int nn = (idx - k * nrow4) << 2;
    float4 v = ((const float4*)src)[idx];
    int kt = k >> 5, kr = k & 31;
    int nt = nn >> 7, nl = nn & 127;
    int nc = nl ^ ((kr & 3) * 8);
    size_t base = (((size_t)kt * ntiles_tot + nt_off + nt) << 13)
                + ((size_t)kr * 128 + nc) * 2;
    unsigned h0, l0, h1, l1, h2, l2, h3, l3;
    split_tf32(v.x, h0, l0);
    split_tf32(v.y, h1, l1);
    split_tf32(v.z, h2, l2);
    split_tf32(v.w, h3, l3);
    *(uint4*)&dst[base]     = make_uint4(h0, l0, h1, l1);
    *(uint4*)&dst[base + 4] = make_uint4(h2, l2, h3, l3);
}

// ---------------- narrow GEMM (BN=128, 2 CTA/SM), grouped-row A and C -------
// A row r lives at A + (r>>7)*gstride  + (r&127)*lda.
// C row r lives at C + (r>>7)*cgstride + (r&127)*N.
// For contiguous layouts pass gstride = 128*lda / cgstride = 128*N.
#define GBM 64
#define GBN 128
#define GBK 32
#define A_BUF_WORDS (GBM * GBK * 2)    // 16KB/stage
#define B_BUF_WORDS (GBK * GBN * 2)    // 32KB/stage
#define GEMM_SMEM ((2 * A_BUF_WORDS + 2 * B_BUF_WORDS) * 4)   // 98304 B

__global__ void __launch_bounds__(256) gemm_tf32x3_pw(
    const float* __restrict__ A, const unsigned* __restrict__ Bp,
    float* __restrict__ C, int M, int N, int K, int lda,
    size_t gstride, size_t cgstride)
{
    extern __shared__ unsigned su[];
    typedef unsigned ABuf[GBM][GBK][2];
    typedef unsigned BBuf[GBK][GBN][2];
    ABuf* As = (ABuf*)su;
    BBuf* Bs = (BBuf*)(su + 2 * A_BUF_WORDS);

    const int tid  = threadIdx.x;
    const int lane = tid & 31;
    const int wid  = tid >> 5;
    const int warp_m = wid & 1;
    const int warp_n = wid >> 1;
    const int row0 = blockIdx.y * GBM;
    const int col0 = blockIdx.x * GBN;
    const int ntiles = N >> 7;

    unsigned sbB[2];
    sbB[0] = (unsigned)__cvta_generic_to_shared(&Bs[0][0][0][0]);
    sbB[1] = (unsigned)__cvta_generic_to_shared(&Bs[1][0][0][0]);

    float4 ra[2];
    float acc[2][4][4];
    #pragma unroll
    for (int i = 0; i < 2; i++)
        #pragma unroll
        for (int j = 0; j < 4; j++)
            #pragma unroll
            for (int l = 0; l < 4; l++) acc[i][j][l] = 0.f;

    {
        const unsigned* btile = Bp + (((size_t)0 * ntiles + (col0 >> 7)) << 13);
        #pragma unroll
        for (int i = 0; i < 8; i++) {
            unsigned d = sbB[0] + (unsigned)(tid + i * 256) * 16u;
            const unsigned* g = btile + (size_t)(tid + i * 256) * 4;
            asm volatile("cp.async.cg.shared.global [%0], [%1], 16;\n"
                         :: "r"(d), "l"(g));
        }
        asm volatile("cp.async.commit_group;\n");
    }
    #pragma unroll
    for (int i = 0; i < 2; i++) {
        int idx = tid + i * 256;
        int m = idx >> 3, k4 = idx & 7;
        int r = row0 + m;
        ra[i] = *(const float4*)&A[(size_t)(r >> 7) * gstride
                                   + (size_t)(r & 127) * lda + k4 * 4];
    }
    #pragma unroll
    for (int i = 0; i < 2; i++) {
        int idx = tid + i * 256;
        int m = idx >> 3, k4 = idx & 7;
        int kc = (k4 * 4) ^ ((m & 7) * 4);
        unsigned h0, l0, h1, l1, h2, l2, h3, l3;
        split_tf32(ra[i].x, h0, l0);
        split_tf32(ra[i].y, h1, l1);
        split_tf32(ra[i].z, h2, l2);
        split_tf32(ra[i].w, h3, l3);
        *(uint4*)&As[0][m][kc][0]     = make_uint4(h0, l0, h1, l1);
        *(uint4*)&As[0][m][kc + 2][0] = make_uint4(h2, l2, h3, l3);
    }
    asm volatile("cp.async.wait_group 0;\n" ::: "memory");
    __syncthreads();

    int buf = 0;
    for (int kk = 0; kk < K; kk += GBK) {
        const int nxt = buf ^ 1;
        const bool more = (kk + GBK < K);

        if (more) {
            const unsigned* btile = Bp
                + (((size_t)((kk + GBK) >> 5) * ntiles + (col0 >> 7)) << 13);
            #pragma unroll
            for (int i = 0; i < 8; i++) {
                unsigned d = sbB[nxt] + (unsigned)(tid + i * 256) * 16u;
                const unsigned* g = btile + (size_t)(tid + i * 256) * 4;
                asm volatile("cp.async.cg.shared.global [%0], [%1], 16;\n"
                             :: "r"(d), "l"(g));
            }
            asm volatile("cp.async.commit_group;\n");
            #pragma unroll
            for (int i = 0; i < 2; i++) {
                int idx = tid + i * 256;
                int m = idx >> 3, k4 = idx & 7;
                int r = row0 + m;
                ra[i] = *(const float4*)&A[(size_t)(r >> 7) * gstride
                                           + (size_t)(r & 127) * lda
                                           + kk + GBK + k4 * 4];
            }
        }

        #pragma unroll
        for (int ks = 0; ks < 4; ks++) {
            int kq = ks * 8 + (lane & 3);
            int swb = (lane & 3) * 8;
            unsigned afH[2][4], afL[2][4];
            unsigned bfH[4][2], bfL[4][2];
            #pragma unroll
            for (int mf = 0; mf < 2; mf++) {
                int m  = warp_m * 32 + mf * 16 + (lane >> 2);
                int sw = (lane >> 2) * 4;
                uint2 a0 = *(const uint2*)&As[buf][m][kq ^ sw][0];
                uint2 a1 = *(const uint2*)&As[buf][m + 8][kq ^ sw][0];
                uint2 a2 = *(const uint2*)&As[buf][m][(kq + 4) ^ sw][0];
                uint2 a3 = *(const uint2*)&As[buf][m + 8][(kq + 4) ^ sw][0];
                afH[mf][0] = a0.x; afL[mf][0] = a0.y;
                afH[mf][1] = a1.x; afL[mf][1] = a1.y;
                afH[mf][2] = a2.x; afL[mf][2] = a2.y;
                afH[mf][3] = a3.x; afL[mf][3] = a3.y;
            }
            #pragma unroll
            for (int nf = 0; nf < 4; nf++) {
                int n = warp_n * 32 + nf * 8 + (lane >> 2);
                uint2 b0 = *(const uint2*)&Bs[buf][kq][n ^ swb][0];
                uint2 b1 = *(const uint2*)&Bs[buf][kq + 4][n ^ swb][0];
                bfH[nf][0] = b0.x; bfL[nf][0] = b0.y;
                bfH[nf][1] = b1.x; bfL[nf][1] = b1.y;
            }
            #pragma unroll
            for (int mf = 0; mf < 2; mf++)
                #pragma unroll
                for (int nf = 0; nf < 4; nf++) {
                    mma_tf32(acc[mf][nf], afL[mf], bfH[nf]);
                    mma_tf32(acc[mf][nf], afH[mf], bfL[nf]);
                    mma_tf32(acc[mf][nf], afH[mf], bfH[nf]);
                }
        }

        if (more) {
            #pragma unroll
            for (int i = 0; i < 2; i++) {
                int idx = tid + i * 256;
                int m = idx >> 3, k4 = idx & 7;
                int kc = (k4 * 4) ^ ((m & 7) * 4);
                unsigned h0, l0, h1, l1, h2, l2, h3, l3;
                split_tf32(ra[i].x, h0, l0);
                split_tf32(ra[i].y, h1, l1);
                split_tf32(ra[i].z, h2, l2);
                split_tf32(ra[i].w, h3, l3);
                *(uint4*)&As[nxt][m][kc][0]     = make_uint4(h0, l0, h1, l1);
                *(uint4*)&As[nxt][m][kc + 2][0] = make_uint4(h2, l2, h3, l3);
            }
            asm volatile("cp.async.wait_group 0;\n" ::: "memory");
        }
        __syncthreads();
        buf = nxt;
    }

    #pragma unroll
    for (int mf = 0; mf < 2; mf++) {
        int row = row0 + warp_m * 32 + mf * 16 + (lane >> 2);
        float* crow0 = C + (size_t)(row >> 7) * cgstride + (size_t)(row & 127) * N;
        int row8 = row + 8;
        float* crow8 = C + (size_t)(row8 >> 7) * cgstride + (size_t)(row8 & 127) * N;
        #pragma unroll
        for (int nf = 0; nf < 4; nf++) {
            int col = col0 + warp_n * 32 + nf * 8 + 2 * (lane & 3);
            *(float2*)&crow0[col] = make_float2(acc[mf][nf][0], acc[mf][nf][1]);
            *(float2*)&crow8[col] = make_float2(acc[mf][nf][2], acc[mf][nf][3]);
        }
    }
}

// ---------------- rmsnorm ----------------------------------------------------
__global__ void __launch_bounds__(256) rmsnorm_kernel(
    float* __restrict__ out, const float* __restrict__ in, const float* __restrict__ w)
{
    int row = blockIdx.x;
    const float* xr = in + (size_t)row * DIMN;
    float vals[8];
    float ss = 0.f;
    #pragma unroll
    for (int t = 0; t < 8; t++) {
        float v = xr[threadIdx.x + t * 256];
        vals[t] = v; ss += v * v;
    }
    float tot = block_sum256(ss);
    float sc = rsqrtf(tot * (1.0f / DIMN) + EPS);
    #pragma unroll
    for (int t = 0; t < 8; t++)
        out[(size_t)row * DIMN + threadIdx.x + t * 256] =
            vals[t] * sc * w[threadIdx.x + t * 256];
}

__global__ void __launch_bounds__(256) add_rmsnorm_kernel(
    float* __restrict__ out, const float* __restrict__ a,
    const float* __restrict__ b, const float* __restrict__ w)
{
    int row = blockIdx.x;
    const float* ar = a + (size_t)row * DIMN;
    const float* br = b + (size_t)row * DIMN;
    float vals[8];
    float ss = 0.f;
    #pragma unroll
    for (int t = 0; t < 8; t++) {
        float v = ar[threadIdx.x + t * 256] + br[threadIdx.x + t * 256];
        vals[t] = v; ss += v * v;
    }
    float tot = block_sum256(ss);
    float sc = rsqrtf(tot * (1.0f / DIMN) + EPS);
    #pragma unroll
    for (int t = 0; t < 8; t++)
        out[(size_t)row * DIMN + threadIdx.x + t * 256] =
            vals[t] * sc * w[threadIdx.x + t * 256];
}

// ---------------- fused-buffer silu: g13[:, :HID] = silu(g1) * g3 -----------
__global__ void __launch_bounds__(256) silu_mul_kernel(float* __restrict__ g13)
{
    int idx = blockIdx.x * 256 + threadIdx.x;
    int n4 = RROWS * HID / 4;
    if (idx >= n4) return;
    int row = idx / (HID / 4);
    int c4  = idx - row * (HID / 4);
    float4* ap = (float4*)&g13[(size_t)row * 2 * HID + c4 * 4];
    float4 av = *ap;
    float4 bv = *(const float4*)&g13[(size_t)row * 2 * HID + HID + c4 * 4];
    av.x = av.x / (1.f + expf(-av.x)) * bv.x;
    av.y = av.y / (1.f + expf(-av.y)) * bv.y;
    av.z = av.z / (1.f + expf(-av.z)) * bv.z;
    av.w = av.w / (1.f + expf(-av.w)) * bv.w;
    *ap = av;
}

// ---------------- build K,V (mkv + xqkv_all chunk slice) with RoPE on K -----
__global__ void __launch_bounds__(256) build_kv_kernel(
    const float* __restrict__ mkv, const float* __restrict__ xqkv_all,
    const float* __restrict__ fc, const float* __restrict__ fs,
    float* __restrict__ k, float* __restrict__ v, int chunk)
{
    int idx = blockIdx.x * 256 + threadIdx.x;
    if (idx >= BATCH * TOTAL * NH * (HD / 2)) return;
    int j   = idx & 63;
    int h   = (idx >> 6) & 15;
    int pos = (idx >> 10) & 255;
    int b   = idx >> 18;
    int col = h * HD + 2 * j;
    const float *sk, *sv;
    if (pos < MEMN) {
        size_t r = (size_t)(b * MEMN + pos) * (2 * DIMN);
        sk = mkv + r + col;
        sv = mkv + r + DIMN + col;
    } else {
        size_t r = (size_t)(b * SEQN + chunk * MEMN + pos - MEMN) * (3 * DIMN);
        sk = xqkv_all + r + DIMN + col;
        sv = xqkv_all + r + 2 * DIMN + col;
    }
    float c = fc[pos * 64 + j], s = fs[pos * 64 + j];
    float kr = sk[0], ki = sk[1];
    size_t o = ((size_t)(b * NH + h) * TOTAL + pos) * HD + 2 * j;
    k[o]     = kr * c - ki * s;
    k[o + 1] = kr * s + ki * c;
    v[o]     = sv[0];
    v[o + 1] = sv[1];
}

// ---------------- fused qk + causal softmax (RoPE on Q load) -----------------
__global__ void __launch_bounds__(256) qk_softmax_kernel(
    const float* __restrict__ xqkv_all, const float* __restrict__ k,
    const float* __restrict__ fc, const float* __restrict__ fs,
    float* __restrict__ s, float scale, int chunk)
{
    __shared__ float Qs[64][64];
    __shared__ float Ks[64][64];
    int bh = blockIdx.y;
    int b = bh >> 4, h = bh & 15;
    int i0 = blockIdx.x * 64;
    int tid = threadIdx.x, tx = tid & 15, ty = tid >> 4;
    const float* qbase = xqkv_all
        + (size_t)(b * SEQN + chunk * MEMN) * (3 * DIMN) + h * HD;
    const float* kb = k + (size_t)bh * TOTAL * HD;

    float acc[4][16];
    #pragma unroll
    for (int r = 0; r < 4; r++)
        #pragma unroll
        for (int c = 0; c < 16; c++) acc[r][c] = 0.f;

    for (int dc = 0; dc < HD; dc += 64) {
        for (int t = tid; t < 64 * 16; t += 256) {
            int r = t >> 4;
            int c4 = (t & 15) * 4;
            float4 a = *(const float4*)&qbase[(size_t)(i0 + r) * (3 * DIMN) + dc + c4];
            int pos = MEMN + i0 + r;
            int j = (dc + c4) >> 1;
            float c0 = fc[pos * 64 + j],     s0 = fs[pos * 64 + j];
            float c1 = fc[pos * 64 + j + 1], s1 = fs[pos * 64 + j + 1];
            Qs[c4 + 0][r] = a.x * c0 - a.y * s0;
            Qs[c4 + 1][r] = a.x * s0 + a.y * c0;
            Qs[c4 + 2][r] = a.z * c1 - a.w * s1;
            Qs[c4 + 3][r] = a.z * s1 + a.w * c1;
        }
        for (int jt = 0; jt < 4; jt++) {
            __syncthreads();
            for (int t = tid; t < 64 * 16; t += 256) {
                int r = t >> 4;
                int c4 = (t & 15) * 4;
                float4 bvec = *(const float4*)&kb[(size_t)(jt * 64 + r) * HD + dc + c4];
                Ks[c4 + 0][r] = bvec.x; Ks[c4 + 1][r] = bvec.y;
                Ks[c4 + 2][r] = bvec.z; Ks[c4 + 3][r] = bvec.w;
            }
            __syncthreads();
            #pragma unroll
            for (int d = 0; d < 64; d++) {
                float4 a = *(const float4*)&Qs[d][ty * 4];
                float4 bvec = *(const float4*)&Ks[d][tx * 4];
                float ar[4] = {a.x, a.y, a.z, a.w};
                float br[4] = {bvec.x, bvec.y, bvec.z, bvec.w};
                #pragma unroll
                for (int r = 0; r < 4; r++)
                    #pragma unroll
                    for (int jc = 0; jc < 4; jc++)
                        acc[r][jt * 4 + jc] += ar[r] * br[jc];
            }
        }
        __syncthreads();
    }

    float sum[4];
    #pragma unroll
    for (int r = 0; r < 4; r++) {
        int ig = i0 + ty * 4 + r;
        int limit = MEMN + ig;
        float ml = -3.4e38f;
        #pragma unroll
        for (int c = 0; c < 16; c++) {
            int j = (c >> 2) * 64 + tx * 4 + (c & 3);
            acc[r][c] = (j <= limit) ? acc[r][c] * scale : -3.4e38f;
            ml = fmaxf(ml, acc[r][c]);
        }
        #pragma unroll
        for (int o = 8; o > 0; o >>= 1)
            ml = fmaxf(ml, __shfl_xor_sync(0xffffffffu, ml, o));
        float sl = 0.f;
        #pragma unroll
        for (int c = 0; c < 16; c++) {
            float e = expf(acc[r][c] - ml);
            acc[r][c] = e;
            sl += e;
        }
        #pragma unroll
        for (int o = 8; o > 0; o >>= 1)
            sl += __shfl_xor_sync(0xffffffffu, sl, o);
        sum[r] = sl;
    }

    #pragma unroll
    for (int r = 0; r < 4; r++) {
        int ig = i0 + ty * 4 + r;
        float inv = 1.f / sum[r];
        #pragma unroll
        for (int jt = 0; jt < 4; jt++) {
            float4 o = make_float4(acc[r][jt * 4 + 0] * inv,
                                   acc[r][jt * 4 + 1] * inv,
                                   acc[r][jt * 4 + 2] * inv,
                                   acc[r][jt * 4 + 3] * inv);
            *(float4*)&s[((size_t)bh * MEMN + ig) * TOTAL + jt * 64 + tx * 4] = o;
        }
    }
}

// ---------------- O = P@V -> y chunk -----------------------------------------
__global__ void __launch_bounds__(256) pv_kernel(
    const float* __restrict__ p, const float* __restrict__ v,
    float* __restrict__ y, int chunk)
{
    __shared__ float Ps[32][64];
    __shared__ float Vs[32][128];
    int bh = blockIdx.y;
    int i0 = blockIdx.x * 64;
    int b = bh >> 4, h = bh & 15;
    int tid = threadIdx.x, tx = tid & 15, ty = tid >> 4;
    const float* pb = p + (size_t)bh * MEMN * TOTAL;
    const float* vb = v + (size_t)bh * TOTAL * HD;
    float acc[4][8] = {};

    for (int j0 = 0; j0 < TOTAL; j0 += 32) {
        for (int t = tid; t < 64 * 8; t += 256) {
            int r = t >> 3;
            int c4 = (t & 7) * 4;
            float4 a = *(const float4*)&pb[(size_t)(i0 + r) * TOTAL + j0 + c4];
            Ps[c4 + 0][r] = a.x; Ps[c4 + 1][r] = a.y;
            Ps[c4 + 2][r] = a.z; Ps[c4 + 3][r] = a.w;
        }
        for (int t = tid; t < 32 * 32; t += 256) {
            int r = t >> 5;
            int c4 = (t & 31) * 4;
            *(float4*)&Vs[r][c4] = *(const float4*)&vb[(size_t)(j0 + r) * HD + c4];
        }
        __syncthreads();
        #pragma unroll
        for (int j = 0; j < 32; j++) {
            float4 a = *(const float4*)&Ps[j][ty * 4];
            float ar[4] = {a.x, a.y, a.z, a.w};
            float4 b0 = *(const float4*)&Vs[j][tx * 8];
            float4 b1 = *(const float4*)&Vs[j][tx * 8 + 4];
            float br[8] = {b0.x, b0.y, b0.z, b0.w, b1.x, b1.y, b1.z, b1.w};
            #pragma unroll
            for (int i = 0; i < 4; i++)
                #pragma unroll
                for (int jc = 0; jc < 8; jc++)
                    acc[i][jc] += ar[i] * br[jc];
        }
        __syncthreads();
    }
    #pragma unroll
    for (int i = 0; i < 4; i++) {
        size_t row = (size_t)b * SEQN + (size_t)chunk * MEMN + i0 + ty * 4 + i;
        float4 o0 = make_float4(acc[i][0], acc[i][1], acc[i][2], acc[i][3]);
        float4 o1 = make_float4(acc[i][4], acc[i][5], acc[i][6], acc[i][7]);
        *(float4*)&y[row * DIMN + h * HD + tx * 8]     = o0;
        *(float4*)&y[row * DIMN + h * HD + tx * 8 + 4] = o1;
    }
}

// ---------------- host orchestration ----------------------------------------
static void launch_gemm_s(const float* A, const unsigned* Bp, float* C,
                          int M, int N, int K, int lda,
                          size_t gstride, size_t cgstride, cudaStream_t st)
{
    dim3 grid(N / GBN, M / GBM);
    gemm_tf32x3_pw<<<grid, 256, GEMM_SMEM, st>>>(A, Bp, C, M, N, K, lda,
                                                 gstride, cgstride);
}

static void launch_presplit(unsigned* dst, const float* src, int K, int N,
                            int nt_off, int ntiles_tot)
{
    int total4 = (K * N) / 4;
    presplit_kernel<<<(total4 + 255) / 256, 256>>>(dst, src, K, N, nt_off, ntiles_tot);
}

extern "C" void kernel_launch(void* const* d_in, const int* in_sizes, int n_in,
                              void* d_out, int out_size)
{
    (void)in_sizes; (void)n_in; (void)out_size;
    const float* x   = (const float*)d_in[0];
    const float* fc  = (const float*)d_in[1];
    const float* fs  = (const float*)d_in[2];
    const float* om0 = (const float*)d_in[3];
    const float* wq  = (const float*)d_in[4];
    const float* wk  = (const float*)d_in[5];
    const float* wv  = (const float*)d_in[6];
    const float* wo  = (const float*)d_in[7];
    /* d_in[8] = wqm: unused */
    const float* wkm = (const float*)d_in[9];
    const float* wvm = (const float*)d_in[10];
    const float* wm  = (const float*)d_in[11];
    const float* ffw = (const float*)d_in[12];
    const float* w1  = (const float*)d_in[13];
    const float* w2  = (const float*)d_in[14];
    const float* w3  = (const float*)d_in[15];
    const float* mnw = (const float*)d_in[16];
    float* out = (float*)d_out;

    static int configured = 0;
    static cudaStream_t s1;
    static cudaEvent_t evP, evW;
    if (!configured) {
        cudaFuncSetAttribute(gemm_tf32x3_pw,
                             cudaFuncAttributeMaxDynamicSharedMemorySize,
                             GEMM_SMEM);
        cudaStreamCreateWithFlags(&s1, cudaStreamNonBlocking);
        cudaEventCreateWithFlags(&evP, cudaEventDisableTiming);
        cudaEventCreateWithFlags(&evW, cudaEventDisableTiming);
        configured = 1;
    }
    cudaStream_t s0 = 0;

    float *om2, *h, *g13, *om4, *mkv, *xqkv, *k, *v, *s, *y;
    cudaGetSymbolAddress((void**)&om2,  g_om2);
    cudaGetSymbolAddress((void**)&h,    g_h);
    cudaGetSymbolAddress((void**)&g13,  g_g13);
    cudaGetSymbolAddress((void**)&om4,  g_om4);
    cudaGetSymbolAddress((void**)&mkv,  g_mkv);
    cudaGetSymbolAddress((void**)&xqkv, g_xqkv_all);
    cudaGetSymbolAddress((void**)&k,    g_k);
    cudaGetSymbolAddress((void**)&v,    g_v);
    cudaGetSymbolAddress((void**)&s,    g_s);
    cudaGetSymbolAddress((void**)&y,    g_y);

    unsigned *pwm, *pwo, *pw2, *pqkv, *pkvm, *pw13;
    cudaGetSymbolAddress((void**)&pwm,  g_p_wm);
    cudaGetSymbolAddress((void**)&pwo,  g_p_wo);
    cudaGetSymbolAddress((void**)&pw2,  g_p_w2);
    cudaGetSymbolAddress((void**)&pqkv, g_p_qkv);
    cudaGetSymbolAddress((void**)&pkvm, g_p_kvm);
    cudaGetSymbolAddress((void**)&pw13, g_p_w13);

    // pre-split + pre-swizzle all weights once per launch
    launch_presplit(pwm,  wm,  DIMN, DIMN, 0, 16);
    launch_presplit(pwo,  wo,  DIMN, DIMN, 0, 16);
    launch_presplit(pw2,  w2,  HID,  DIMN, 0, 16);
    launch_presplit(pqkv, wq,  DIMN, DIMN, 0,  48);
    launch_presplit(pqkv, wk,  DIMN, DIMN, 16, 48);
    launch_presplit(pqkv, wv,  DIMN, DIMN, 32, 48);
    launch_presplit(pkvm, wkm, DIMN, DIMN, 0,  32);
    launch_presplit(pkvm, wvm, DIMN, DIMN, 16, 32);
    launch_presplit(pw13, w1,  DIMN, HID,  0,  88);
    launch_presplit(pw13, w3,  DIMN, HID,  44, 88);

    const size_t CONT   = (size_t)128 * DIMN;
    const size_t CONT3  = (size_t)128 * 3 * DIMN;
    const size_t CONT2  = (size_t)128 * 2 * DIMN;
    const size_t CONT13i = (size_t)128 * 2 * HID;
    const size_t SEQSTR = (size_t)SEQN * DIMN;

    // ALL chunks' qkv projection in ONE giant GEMM (x rows contiguous)
    launch_gemm_s(x, pqkv, xqkv, BATCH * SEQN, 3 * DIMN, DIMN,
                  DIMN, CONT, CONT3, s0);

    const float scale = 0.08838834764831845f;   // 1/sqrt(128)

    for (int c = 0; c < NCHUNK; c++) {
        const float* omp   = c ? (y + (size_t)(c - 1) * MEMN * DIMN) : om0;
        size_t       omstr = c ? SEQSTR : CONT;

        // memory-stream FFN chain (s0)
        launch_gemm_s(omp, pwm, om2, RROWS, DIMN, DIMN, DIMN, omstr, CONT, s0);
        rmsnorm_kernel<<<RROWS, 256, 0, s0>>>(h, om2, ffw);
        launch_gemm_s(h, pw13, g13, RROWS, 2 * HID, DIMN, DIMN, CONT, CONT13i, s0);
        silu_mul_kernel<<<(RROWS * HID / 4 + 255) / 256, 256, 0, s0>>>(g13);
        launch_gemm_s(g13, pw2, h, RROWS, DIMN, HID, 2 * HID, CONT13i, CONT, s0);
        add_rmsnorm_kernel<<<RROWS, 256, 0, s0>>>(om4, om2, h, mnw);
        launch_gemm_s(om4, pkvm, mkv, RROWS, 2 * DIMN, DIMN, DIMN, CONT, CONT2, s0);

        // assemble roped k/v; attention (s0)
        build_kv_kernel<<<(BATCH * TOTAL * NH * 64 + 255) / 256, 256, 0, s0>>>(
            mkv, xqkv, fc, fs, k, v, c);
        {
            dim3 g(2, BATCH * NH);
            qk_softmax_kernel<<<g, 256, 0, s0>>>(xqkv, k, fc, fs, s, scale, c);
        }
        {
            dim3 g(2, BATCH * NH);
            pv_kernel<<<g, 256, 0, s0>>>(s, v, y, c);
        }

        // stream this chunk's final projection on s1 (fills s0's bubbles)
        cudaEventRecord(evP, s0);
        cudaStreamWaitEvent(s1, evP, 0);
        launch_gemm_s(y + (size_t)c * MEMN * DIMN, pwo,
                      out + (size_t)c * MEMN * DIMN,
                      RROWS, DIMN, DIMN, DIMN, SEQSTR, SEQSTR, s1);
    }

    // join s1 back so stream-0 completion covers all wo slices
    cudaEventRecord(evW, s1);
    cudaStreamWaitEvent(s0, evW, 0);
}